// round 8
// baseline (speedup 1.0000x reference)
#include <cuda_runtime.h>
#include <cuda_bf16.h>
#include <cuda_fp8.h>
#include <cstdint>
#include <math.h>

#define B_ROWS 32768
#define C_CLS  1000
#define KPAD   1024
#define EPSU   1e-6f
#define NORMF  0.031622776601683794f   // 1/sqrt(1000)
#define INV_C  0.001f
#define SA     128.0f                  // fp8 scale for A / E
#define SB     256.0f                  // fp8 scale for centered B residuals
#define DEQ    (1.0f / (128.0f * 256.0f))

// ---------------- scratch (__device__ globals; no allocations) --------------
__device__ uint8_t g_Af8[(size_t)B_ROWS * KPAD];   // p_tar  fp8 x128, padded
__device__ uint8_t g_Ef8[(size_t)B_ROWS * KPAD];   // E      fp8 x128, padded
__device__ uint8_t g_B1f8[(size_t)KPAD * KPAD];    // (bank - m1) x256  [n][k]
__device__ uint8_t g_B2f8[(size_t)KPAD * KPAD];    // (bank^T - m2) x256 [j][k]
__device__ float   g_BT[(size_t)KPAD * KPAD];      // bank^T fp32 staging
__device__ float   g_m1[KPAD];                     // row means of bank
__device__ float   g_m2[KPAD];                     // raw col sums of bank
__device__ float   g_rowsum[B_ROWS];
__device__ float   g_sums[(size_t)C_CLS * C_CLS];
__device__ float   g_count[C_CLS];

// ---------------- helpers ----------------------------------------------------
__device__ __forceinline__ uint16_t f2_fp8x2(float lo, float hi) {
    __nv_fp8x2_storage_t r =
        __nv_cvt_float2_to_fp8x2(make_float2(lo, hi), __NV_SATFINITE, __NV_E4M3);
    return (uint16_t)r;
}
__device__ __forceinline__ uint32_t smem_u32(const void* p) {
    uint32_t a;
    asm("{ .reg .u64 t; cvta.to.shared.u64 t, %1; cvt.u32.u64 %0, t; }"
        : "=r"(a) : "l"(p));
    return a;
}
__device__ __forceinline__ void ldmx4(uint32_t* r, uint32_t addr) {
    asm volatile("ldmatrix.sync.aligned.m8n8.x4.shared.b16 {%0,%1,%2,%3}, [%4];"
                 : "=r"(r[0]), "=r"(r[1]), "=r"(r[2]), "=r"(r[3]) : "r"(addr));
}
__device__ __forceinline__ void mma_fp8(float* c, const uint32_t* a,
                                        uint32_t b0, uint32_t b1) {
    asm volatile("mma.sync.aligned.m16n8k32.row.col.f32.e4m3.e4m3.f32 "
                 "{%0,%1,%2,%3}, {%4,%5,%6,%7}, {%8,%9}, {%0,%1,%2,%3};"
                 : "+f"(c[0]), "+f"(c[1]), "+f"(c[2]), "+f"(c[3])
                 : "r"(a[0]), "r"(a[1]), "r"(a[2]), "r"(a[3]), "r"(b0), "r"(b1));
}
#define CP16(dst, src) \
    asm volatile("cp.async.cg.shared.global [%0], [%1], 16;" :: "r"(dst), "l"(src))
#define CP_COMMIT() asm volatile("cp.async.commit_group;")
#define CP_WAIT1()  asm volatile("cp.async.wait_group 1;")

// ---------------------------------------------------------------------------
__global__ void zero_kernel() {
    int i = blockIdx.x * blockDim.x + threadIdx.x;
    if (i < C_CLS * C_CLS) g_sums[i] = 0.0f;
    if (i < B_ROWS)        g_rowsum[i] = 0.0f;
    if (i < C_CLS)         g_count[i] = 0.0f;
    if (i < KPAD)          g_m2[i] = 0.0f;
}

// B1: row means + centered fp8 residual rows of bank  [n][k]
__global__ void __launch_bounds__(128) convB1_kernel(const float* __restrict__ bank) {
    const int n = blockIdx.x;     // 0..1023
    const int t = threadIdx.x;
    uint32_t* dst = reinterpret_cast<uint32_t*>(g_B1f8 + (size_t)n * KPAD);
    if (n >= C_CLS) {
        for (int u = t; u < KPAD / 4; u += 128) dst[u] = 0u;
        if (t == 0) g_m1[n] = 0.0f;
        return;
    }
    const float* row = bank + (size_t)n * C_CLS;
    float s = 0.0f;
    for (int k = t; k < C_CLS; k += 128) s += row[k];
    #pragma unroll
    for (int o = 16; o > 0; o >>= 1) s += __shfl_xor_sync(0xFFFFFFFFu, s, o);
    __shared__ float sw[4];
    if ((t & 31) == 0) sw[t >> 5] = s;
    __syncthreads();
    const float m = (sw[0] + sw[1] + sw[2] + sw[3]) * INV_C;
    if (t == 0) g_m1[n] = m;
    for (int u = t; u < KPAD / 4; u += 128) {
        int k = 4 * u;
        float4 v = make_float4(0.f, 0.f, 0.f, 0.f);
        if (k + 3 < C_CLS) v = *(const float4*)(row + k);  // C_CLS % 4 == 0
        uint16_t lo = f2_fp8x2((k < C_CLS) ? (v.x - m) * SB : 0.f,
                               (k < C_CLS) ? (v.y - m) * SB : 0.f);
        uint16_t hi = f2_fp8x2((k < C_CLS) ? (v.z - m) * SB : 0.f,
                               (k < C_CLS) ? (v.w - m) * SB : 0.f);
        dst[u] = (uint32_t)lo | ((uint32_t)hi << 16);
    }
}

// T1: tiled transpose bank -> g_BT (fp32) + column-sum atomics into g_m2
__global__ void __launch_bounds__(256) transT_kernel(const float* __restrict__ bank) {
    __shared__ float tile[32][33];
    const int tk = blockIdx.y * 32;
    const int tj = blockIdx.x * 32;
    const int jx = threadIdx.x & 31;
    const int ky = threadIdx.x >> 5;
    #pragma unroll
    for (int s = 0; s < 4; s++) {
        int k = tk + ky + s * 8, j = tj + jx;
        tile[ky + s * 8][jx] = (k < C_CLS && j < C_CLS)
                             ? bank[(size_t)k * C_CLS + j] : 0.0f;
    }
    __syncthreads();
    #pragma unroll
    for (int s = 0; s < 4; s++) {
        int j = tj + ky + s * 8, k = tk + jx;
        g_BT[(size_t)j * KPAD + k] = tile[jx][ky + s * 8];
    }
    float ps = 0.0f;
    #pragma unroll
    for (int s = 0; s < 4; s++) ps += tile[ky + s * 8][jx];
    __syncthreads();
    tile[ky][jx] = ps;
    __syncthreads();
    if (ky == 0) {
        float tot = 0.0f;
        #pragma unroll
        for (int y = 0; y < 8; y++) tot += tile[y][jx];
        if (tj + jx < C_CLS) atomicAdd(&g_m2[tj + jx], tot);
    }
}

// T2: centered fp8 residual rows of bank^T  [j][k]
__global__ void __launch_bounds__(128) convB2_kernel() {
    const int j = blockIdx.x;
    const int t = threadIdx.x;
    uint32_t* dst = reinterpret_cast<uint32_t*>(g_B2f8 + (size_t)j * KPAD);
    if (j >= C_CLS) {
        for (int u = t; u < KPAD / 4; u += 128) dst[u] = 0u;
        return;
    }
    const float m = g_m2[j] * INV_C;
    const float* row = g_BT + (size_t)j * KPAD;
    for (int u = t; u < KPAD / 4; u += 128) {
        int k = 4 * u;
        if (k + 3 < C_CLS) {
            float4 v = *(const float4*)(row + k);
            uint16_t lo = f2_fp8x2((v.x - m) * SB, (v.y - m) * SB);
            uint16_t hi = f2_fp8x2((v.z - m) * SB, (v.w - m) * SB);
            dst[u] = (uint32_t)lo | ((uint32_t)hi << 16);
        } else {
            dst[u] = 0u;
        }
    }
}

// prep: p_tar -> fp8 (g_Af8) + dual argmax + agreement + fused scatter-add
__global__ void __launch_bounds__(256) prep_kernel(const float* __restrict__ p_tar,
                                                   const float* __restrict__ p_vlm) {
    const int row = blockIdx.x;
    const int t   = threadIdx.x;
    const float4* pt4 = reinterpret_cast<const float4*>(p_tar + (size_t)row * C_CLS);
    const float4* pv4 = reinterpret_cast<const float4*>(p_vlm + (size_t)row * C_CLS);
    uint32_t* arow = reinterpret_cast<uint32_t*>(g_Af8 + (size_t)row * KPAD);

    float vt = -1.0f, vv = -1.0f;
    int   it = 0,     iv = 0;
    float4 a = make_float4(0.f, 0.f, 0.f, 0.f);
    const int k = 4 * t;
    const bool act = (t < KPAD / 4) && (k < C_CLS);
    if (act) {
        a = pt4[t];
        float4 b = pv4[t];
        if (a.x > vt) { vt = a.x; it = k; }
        if (a.y > vt) { vt = a.y; it = k + 1; }
        if (a.z > vt) { vt = a.z; it = k + 2; }
        if (a.w > vt) { vt = a.w; it = k + 3; }
        if (b.x > vv) { vv = b.x; iv = k; }
        if (b.y > vv) { vv = b.y; iv = k + 1; }
        if (b.z > vv) { vv = b.z; iv = k + 2; }
        if (b.w > vv) { vv = b.w; iv = k + 3; }
        uint16_t lo = f2_fp8x2(a.x * SA, a.y * SA);
        uint16_t hi = f2_fp8x2(a.z * SA, a.w * SA);
        arow[t] = (uint32_t)lo | ((uint32_t)hi << 16);
    } else if (t < KPAD / 4) {
        arow[t] = 0u;
    }
    const int lane = t & 31;
    #pragma unroll
    for (int off = 16; off > 0; off >>= 1) {
        float ov = __shfl_down_sync(0xFFFFFFFFu, vt, off);
        int   oi = __shfl_down_sync(0xFFFFFFFFu, it, off);
        if (ov > vt || (ov == vt && oi < it)) { vt = ov; it = oi; }
        ov = __shfl_down_sync(0xFFFFFFFFu, vv, off);
        oi = __shfl_down_sync(0xFFFFFFFFu, iv, off);
        if (ov > vv || (ov == vv && oi < iv)) { vv = ov; iv = oi; }
    }
    __shared__ float swt[8], swv[8];
    __shared__ int   sit[8], siv[8];
    __shared__ int   s_lab;
    if (lane == 0) { swt[t >> 5] = vt; sit[t >> 5] = it; swv[t >> 5] = vv; siv[t >> 5] = iv; }
    __syncthreads();
    if (t == 0) {
        float bt = swt[0], bv = swv[0];
        int   bi = sit[0], bj = siv[0];
        #pragma unroll
        for (int w = 1; w < 8; w++) {
            if (swt[w] > bt || (swt[w] == bt && sit[w] < bi)) { bt = swt[w]; bi = sit[w]; }
            if (swv[w] > bv || (swv[w] == bv && siv[w] < bj)) { bv = swv[w]; bj = siv[w]; }
        }
        if (bi == bj) { s_lab = bi; atomicAdd(&g_count[bi], 1.0f); }
        else          { s_lab = -1; }
    }
    __syncthreads();
    const int c = s_lab;
    if (c >= 0 && act) {   // fused scatter (rare: ~B/C rows agree)
        float* dst = g_sums + (size_t)c * C_CLS + k;
        atomicAdd(dst + 0, a.x);
        if (k + 1 < C_CLS) atomicAdd(dst + 1, a.y);
        if (k + 2 < C_CLS) atomicAdd(dst + 2, a.z);
        if (k + 3 < C_CLS) atomicAdd(dst + 3, a.w);
    }
}

__global__ void bank_kernel(const float* __restrict__ bank,
                            const float* __restrict__ alpha,
                            float* __restrict__ out_bank) {
    int i = blockIdx.x * blockDim.x + threadIdx.x;
    if (i >= C_CLS * C_CLS) return;
    int   c   = i / C_CLS;
    float a   = alpha[0];
    float cnt = g_count[c];
    float b   = bank[i];
    out_bank[i] = (cnt > 0.0f) ? (a * b + (1.0f - a) * (g_sums[i] / cnt)) : b;
}

// ---------------------------------------------------------------------------
// fp8 HMMA GEMM (NT): D[bm:+128, bn:+128] = A * B^T (residual part)
// 256 thr, 8 warps (4m x 2n), warp tile 32x64, 128-byte K chunks,
// cp.async 3-stage, ONE sync per chunk, 2 CTAs/SM
#define BM     128
#define BN     128
#define BKB    128                   // k bytes per chunk (full row)
#define STAGES 3
#define LDSPB  144                   // padded smem row stride (bytes), 9*16
#define NCH    (KPAD / BKB)          // 8
#define STA    (BM * LDSPB)          // 18432
#define STB    (BN * LDSPB)          // 18432
#define STT    (STA + STB)           // 36864
#define SMEMT  (STAGES * STT)        // 110592

__global__ void __launch_bounds__(256, 2)
gemm_fp8(const float* __restrict__ p_vlm,
         float* __restrict__ out,
         int mode) {
    extern __shared__ char smem[];
    const uint32_t sb = smem_u32(smem);

    const uint8_t* __restrict__ A  = (mode == 1) ? g_Af8  : g_Ef8;
    const uint8_t* __restrict__ Bm = (mode == 1) ? g_B1f8 : g_B2f8;

    const int t   = threadIdx.x;
    const int wid = t >> 5;
    const int l   = t & 31;
    const int wm  = wid >> 1;            // 0..3 -> m offset wm*32
    const int wn  = wid & 1;             // 0..1 -> n offset wn*64
    const int bm  = blockIdx.y * BM;
    const int bn  = blockIdx.x * BN;

    // loader mapping: 128 rows, 2 threads/row, each thread 4 x 16B
    const int lr = t >> 1;               // row 0..127
    const int lu = (t & 1) * 64;         // byte offset 0 or 64

    const uint8_t* gAp = A  + (size_t)(bm + lr) * KPAD + lu;
    const uint8_t* gBp = Bm + (size_t)(bn + lr) * KPAD + lu;
    const uint32_t sAp = sb + lr * LDSPB + lu;
    const uint32_t sBp = sb + STA + lr * LDSPB + lu;

    float acc[2][8][4];
    #pragma unroll
    for (int mi = 0; mi < 2; mi++)
        #pragma unroll
        for (int ni = 0; ni < 8; ni++)
            #pragma unroll
            for (int kk = 0; kk < 4; kk++) acc[mi][ni][kk] = 0.0f;

    const int aRow = wm * 32 + (l & 15);
    const int aOff = (l & 16) ? 16 : 0;   // bytes
    const int bRow = wn * 64 + (l & 7) + ((l & 16) ? 8 : 0);
    const int bOff = (l & 8) ? 16 : 0;    // bytes

    auto load_stage = [&](int chunk, int buf) {
        const int kc = chunk * BKB;
        const uint32_t off = buf * STT;
        #pragma unroll
        for (int i = 0; i < 4; i++)
            CP16(sAp + off + i * 16, gAp + kc + i * 16);
        #pragma unroll
        for (int i = 0; i < 4; i++)
            CP16(sBp + off + i * 16, gBp + kc + i * 16);
    };

    #pragma unroll
    for (int s = 0; s < STAGES - 1; ++s) { load_stage(s, s); CP_COMMIT(); }

    for (int c = 0; c < NCH; ++c) {
        CP_WAIT1();
        __syncthreads();                 // single barrier per chunk
        const int buf = (c % STAGES);
        const uint32_t baseA = sb + buf * STT;
        const uint32_t baseB = baseA + STA;

        #pragma unroll
        for (int s = 0; s < 4; ++s) {    // four k32 steps per chunk
            uint32_t af[2][4];
            #pragma unroll
            for (int mi = 0; mi < 2; mi++)
                ldmx4(af[mi], baseA + (aRow + mi * 16) * LDSPB + s * 32 + aOff);
            uint32_t bf[4][4];
            #pragma unroll
            for (int g = 0; g < 4; g++)
                ldmx4(bf[g], baseB + (bRow + g * 16) * LDSPB + s * 32 + bOff);
            #pragma unroll
            for (int mi = 0; mi < 2; mi++)
                #pragma unroll
                for (int g = 0; g < 4; g++) {
                    mma_fp8(acc[mi][2 * g],     af[mi], bf[g][0], bf[g][1]);
                    mma_fp8(acc[mi][2 * g + 1], af[mi], bf[g][2], bf[g][3]);
                }
        }

        const int nc_ = c + STAGES - 1;
        if (nc_ < NCH) { load_stage(nc_, nc_ % STAGES); }
        CP_COMMIT();
    }

    // ---- epilogue ----
    // rows: bm + wm*32 + mi*16 + (l>>2) + h*8 ; cols: bn + wn*64 + ni*8 + (l&3)*2
    if (mode == 1) {
        #pragma unroll
        for (int mi = 0; mi < 2; mi++) {
            #pragma unroll
            for (int h = 0; h < 2; h++) {
                const int row = bm + wm * 32 + mi * 16 + (l >> 2) + h * 8;
                float rs = 0.0f;
                #pragma unroll
                for (int ni = 0; ni < 8; ni++) {
                    const int col = bn + wn * 64 + ni * 8 + (l & 3) * 2;
                    float e0 = 0.0f, e1 = 0.0f;
                    if (col < C_CLS)
                        e0 = __expf((g_m1[col] + acc[mi][ni][h * 2 + 0] * DEQ) * NORMF);
                    if (col + 1 < C_CLS)
                        e1 = __expf((g_m1[col + 1] + acc[mi][ni][h * 2 + 1] * DEQ) * NORMF);
                    *(uint16_t*)&g_Ef8[(size_t)row * KPAD + col] =
                        f2_fp8x2(e0 * SA, e1 * SA);
                    rs += e0 + e1;
                }
                rs += __shfl_xor_sync(0xFFFFFFFFu, rs, 1);
                rs += __shfl_xor_sync(0xFFFFFFFFu, rs, 2);
                if ((l & 3) == 0) atomicAdd(&g_rowsum[row], rs);
            }
        }
    } else {
        #pragma unroll
        for (int mi = 0; mi < 2; mi++) {
            #pragma unroll
            for (int h = 0; h < 2; h++) {
                const int row = bm + wm * 32 + mi * 16 + (l >> 2) + h * 8;
                const float inv = 1.0f / g_rowsum[row];
                const float* pvrow = p_vlm + (size_t)row * C_CLS;
                float*       orow  = out   + (size_t)row * C_CLS;
                #pragma unroll
                for (int ni = 0; ni < 8; ni++) {
                    const int col = bn + wn * 64 + ni * 8 + (l & 3) * 2;
                    #pragma unroll
                    for (int e = 0; e < 2; e++) {
                        int n = col + e;
                        if (n < C_CLS) {
                            float pt  = g_m2[n] * INV_C
                                      + acc[mi][ni][h * 2 + e] * DEQ * inv;
                            float pv  = __ldg(pvrow + n);
                            float eut = __expf(pt * __logf(pt + EPSU));
                            float euv = __expf(pv * __logf(pv + EPSU));
                            orow[n] = (eut * pt + euv * pv) / (eut + euv);
                        }
                    }
                }
            }
        }
    }
}

// ---------------------------------------------------------------------------
extern "C" void kernel_launch(void* const* d_in, const int* in_sizes, int n_in,
                              void* d_out, int out_size) {
    const float* p_tar = (const float*)d_in[0];
    const float* p_vlm = (const float*)d_in[1];
    const float* alpha = (const float*)d_in[2];
    const float* bank  = (const float*)d_in[3];
    float* out      = (float*)d_out;                       // p_mix [B,C]
    float* out_bank = out + (size_t)B_ROWS * C_CLS;        // bank_new [C,C]

    static int attr_set = 0;
    if (!attr_set) {
        cudaFuncSetAttribute(gemm_fp8, cudaFuncAttributeMaxDynamicSharedMemorySize,
                             SMEMT);
        attr_set = 1;
    }

    dim3 gg(KPAD / BN, B_ROWS / BM);  // (8, 256)

    zero_kernel<<<(C_CLS * C_CLS + 255) / 256, 256>>>();          // 1
    convB1_kernel<<<KPAD, 128>>>(bank);                           // 2
    prep_kernel<<<B_ROWS, 256>>>(p_tar, p_vlm);                   // 3
    gemm_fp8<<<gg, 256, SMEMT>>>(nullptr, nullptr, 1);            // 4 <- ncu capture
    transT_kernel<<<dim3(32, 32), 256>>>(bank);                   // 5
    convB2_kernel<<<KPAD, 128>>>();                               // 6
    gemm_fp8<<<gg, 256, SMEMT>>>(p_vlm, out, 2);                  // 7
    bank_kernel<<<(C_CLS * C_CLS + 255) / 256, 256>>>(bank, alpha, out_bank); // 8
}

// round 9
// speedup vs baseline: 1.1994x; 1.1994x over previous
#include <cuda_runtime.h>
#include <cuda_bf16.h>
#include <cuda_fp8.h>
#include <cstdint>
#include <math.h>

#define B_ROWS 32768
#define C_CLS  1000
#define KPAD   1024
#define EPSU   1e-6f
#define NORMF  0.031622776601683794f   // 1/sqrt(1000)
#define INV_C  0.001f
#define SA     128.0f                  // fp8 scale for A / E
#define SB     256.0f                  // fp8 scale for centered B residuals
#define DEQ    (1.0f / (128.0f * 256.0f))

// ---------------- scratch (__device__ globals; no allocations) --------------
__device__ uint8_t g_Af8[(size_t)B_ROWS * KPAD];   // p_tar  fp8 x128, padded
__device__ uint8_t g_Ef8[(size_t)B_ROWS * KPAD];   // E      fp8 x128, padded
__device__ uint8_t g_B1f8[(size_t)KPAD * KPAD];    // (bank - m1) x256  [n][k]
__device__ uint8_t g_B2f8[(size_t)KPAD * KPAD];    // (bank^T - m2) x256 [j][k]
__device__ float   g_BT[(size_t)KPAD * KPAD];      // bank^T fp32 staging
__device__ float   g_m1[KPAD];                     // row means of bank
__device__ float   g_m2[KPAD];                     // raw col sums of bank
__device__ float   g_rowsum[B_ROWS];
__device__ float   g_sums[(size_t)C_CLS * C_CLS];
__device__ float   g_count[C_CLS];

// ---------------- helpers ----------------------------------------------------
__device__ __forceinline__ uint16_t f2_fp8x2(float lo, float hi) {
    __nv_fp8x2_storage_t r =
        __nv_cvt_float2_to_fp8x2(make_float2(lo, hi), __NV_SATFINITE, __NV_E4M3);
    return (uint16_t)r;
}
__device__ __forceinline__ uint32_t smem_u32(const void* p) {
    uint32_t a;
    asm("{ .reg .u64 t; cvta.to.shared.u64 t, %1; cvt.u32.u64 %0, t; }"
        : "=r"(a) : "l"(p));
    return a;
}
__device__ __forceinline__ void ldmx4(uint32_t* r, uint32_t addr) {
    asm volatile("ldmatrix.sync.aligned.m8n8.x4.shared.b16 {%0,%1,%2,%3}, [%4];"
                 : "=r"(r[0]), "=r"(r[1]), "=r"(r[2]), "=r"(r[3]) : "r"(addr));
}
__device__ __forceinline__ void mma_fp8(float* c, const uint32_t* a,
                                        uint32_t b0, uint32_t b1) {
    asm volatile("mma.sync.aligned.m16n8k32.row.col.f32.e4m3.e4m3.f32 "
                 "{%0,%1,%2,%3}, {%4,%5,%6,%7}, {%8,%9}, {%0,%1,%2,%3};"
                 : "+f"(c[0]), "+f"(c[1]), "+f"(c[2]), "+f"(c[3])
                 : "r"(a[0]), "r"(a[1]), "r"(a[2]), "r"(a[3]), "r"(b0), "r"(b1));
}
#define CP16(dst, src) \
    asm volatile("cp.async.cg.shared.global [%0], [%1], 16;" :: "r"(dst), "l"(src))
#define CP_COMMIT() asm volatile("cp.async.commit_group;")
#define CP_WAIT2()  asm volatile("cp.async.wait_group 2;")

// ---------------------------------------------------------------------------
__global__ void zero_kernel() {
    int i = blockIdx.x * blockDim.x + threadIdx.x;
    if (i < C_CLS * C_CLS) g_sums[i] = 0.0f;
    if (i < B_ROWS)        g_rowsum[i] = 0.0f;
    if (i < C_CLS)         g_count[i] = 0.0f;
    if (i < KPAD)          g_m2[i] = 0.0f;
}

// B1: row means + centered fp8 residual rows of bank  [n][k]
__global__ void __launch_bounds__(128) convB1_kernel(const float* __restrict__ bank) {
    const int n = blockIdx.x;     // 0..1023
    const int t = threadIdx.x;
    uint32_t* dst = reinterpret_cast<uint32_t*>(g_B1f8 + (size_t)n * KPAD);
    if (n >= C_CLS) {
        for (int u = t; u < KPAD / 4; u += 128) dst[u] = 0u;
        if (t == 0) g_m1[n] = 0.0f;
        return;
    }
    const float* row = bank + (size_t)n * C_CLS;
    float s = 0.0f;
    for (int k = t; k < C_CLS; k += 128) s += row[k];
    #pragma unroll
    for (int o = 16; o > 0; o >>= 1) s += __shfl_xor_sync(0xFFFFFFFFu, s, o);
    __shared__ float sw[4];
    if ((t & 31) == 0) sw[t >> 5] = s;
    __syncthreads();
    const float m = (sw[0] + sw[1] + sw[2] + sw[3]) * INV_C;
    if (t == 0) g_m1[n] = m;
    for (int u = t; u < KPAD / 4; u += 128) {
        int k = 4 * u;
        float4 v = make_float4(0.f, 0.f, 0.f, 0.f);
        if (k + 3 < C_CLS) v = *(const float4*)(row + k);  // C_CLS % 4 == 0
        uint16_t lo = f2_fp8x2((k < C_CLS) ? (v.x - m) * SB : 0.f,
                               (k < C_CLS) ? (v.y - m) * SB : 0.f);
        uint16_t hi = f2_fp8x2((k < C_CLS) ? (v.z - m) * SB : 0.f,
                               (k < C_CLS) ? (v.w - m) * SB : 0.f);
        dst[u] = (uint32_t)lo | ((uint32_t)hi << 16);
    }
}

// T1: tiled transpose bank -> g_BT (fp32) + column-sum atomics into g_m2
__global__ void __launch_bounds__(256) transT_kernel(const float* __restrict__ bank) {
    __shared__ float tile[32][33];
    const int tk = blockIdx.y * 32;
    const int tj = blockIdx.x * 32;
    const int jx = threadIdx.x & 31;
    const int ky = threadIdx.x >> 5;
    #pragma unroll
    for (int s = 0; s < 4; s++) {
        int k = tk + ky + s * 8, j = tj + jx;
        tile[ky + s * 8][jx] = (k < C_CLS && j < C_CLS)
                             ? bank[(size_t)k * C_CLS + j] : 0.0f;
    }
    __syncthreads();
    #pragma unroll
    for (int s = 0; s < 4; s++) {
        int j = tj + ky + s * 8, k = tk + jx;
        g_BT[(size_t)j * KPAD + k] = tile[jx][ky + s * 8];
    }
    float ps = 0.0f;
    #pragma unroll
    for (int s = 0; s < 4; s++) ps += tile[ky + s * 8][jx];
    __syncthreads();
    tile[ky][jx] = ps;
    __syncthreads();
    if (ky == 0) {
        float tot = 0.0f;
        #pragma unroll
        for (int y = 0; y < 8; y++) tot += tile[y][jx];
        if (tj + jx < C_CLS) atomicAdd(&g_m2[tj + jx], tot);
    }
}

// T2: centered fp8 residual rows of bank^T  [j][k]
__global__ void __launch_bounds__(128) convB2_kernel() {
    const int j = blockIdx.x;
    const int t = threadIdx.x;
    uint32_t* dst = reinterpret_cast<uint32_t*>(g_B2f8 + (size_t)j * KPAD);
    if (j >= C_CLS) {
        for (int u = t; u < KPAD / 4; u += 128) dst[u] = 0u;
        return;
    }
    const float m = g_m2[j] * INV_C;
    const float* row = g_BT + (size_t)j * KPAD;
    for (int u = t; u < KPAD / 4; u += 128) {
        int k = 4 * u;
        if (k + 3 < C_CLS) {
            float4 v = *(const float4*)(row + k);
            uint16_t lo = f2_fp8x2((v.x - m) * SB, (v.y - m) * SB);
            uint16_t hi = f2_fp8x2((v.z - m) * SB, (v.w - m) * SB);
            dst[u] = (uint32_t)lo | ((uint32_t)hi << 16);
        } else {
            dst[u] = 0u;
        }
    }
}

// prep: p_tar -> fp8 (g_Af8) + dual argmax + agreement + fused scatter-add
__global__ void __launch_bounds__(256) prep_kernel(const float* __restrict__ p_tar,
                                                   const float* __restrict__ p_vlm) {
    const int row = blockIdx.x;
    const int t   = threadIdx.x;
    const float4* pt4 = reinterpret_cast<const float4*>(p_tar + (size_t)row * C_CLS);
    const float4* pv4 = reinterpret_cast<const float4*>(p_vlm + (size_t)row * C_CLS);
    uint32_t* arow = reinterpret_cast<uint32_t*>(g_Af8 + (size_t)row * KPAD);

    float vt = -1.0f, vv = -1.0f;
    int   it = 0,     iv = 0;
    float4 a = make_float4(0.f, 0.f, 0.f, 0.f);
    const int k = 4 * t;
    const bool act = (t < KPAD / 4) && (k < C_CLS);
    if (act) {
        a = pt4[t];
        float4 b = pv4[t];
        if (a.x > vt) { vt = a.x; it = k; }
        if (a.y > vt) { vt = a.y; it = k + 1; }
        if (a.z > vt) { vt = a.z; it = k + 2; }
        if (a.w > vt) { vt = a.w; it = k + 3; }
        if (b.x > vv) { vv = b.x; iv = k; }
        if (b.y > vv) { vv = b.y; iv = k + 1; }
        if (b.z > vv) { vv = b.z; iv = k + 2; }
        if (b.w > vv) { vv = b.w; iv = k + 3; }
        uint16_t lo = f2_fp8x2(a.x * SA, a.y * SA);
        uint16_t hi = f2_fp8x2(a.z * SA, a.w * SA);
        arow[t] = (uint32_t)lo | ((uint32_t)hi << 16);
    } else if (t < KPAD / 4) {
        arow[t] = 0u;
    }
    const int lane = t & 31;
    #pragma unroll
    for (int off = 16; off > 0; off >>= 1) {
        float ov = __shfl_down_sync(0xFFFFFFFFu, vt, off);
        int   oi = __shfl_down_sync(0xFFFFFFFFu, it, off);
        if (ov > vt || (ov == vt && oi < it)) { vt = ov; it = oi; }
        ov = __shfl_down_sync(0xFFFFFFFFu, vv, off);
        oi = __shfl_down_sync(0xFFFFFFFFu, iv, off);
        if (ov > vv || (ov == vv && oi < iv)) { vv = ov; iv = oi; }
    }
    __shared__ float swt[8], swv[8];
    __shared__ int   sit[8], siv[8];
    __shared__ int   s_lab;
    if (lane == 0) { swt[t >> 5] = vt; sit[t >> 5] = it; swv[t >> 5] = vv; siv[t >> 5] = iv; }
    __syncthreads();
    if (t == 0) {
        float bt = swt[0], bv = swv[0];
        int   bi = sit[0], bj = siv[0];
        #pragma unroll
        for (int w = 1; w < 8; w++) {
            if (swt[w] > bt || (swt[w] == bt && sit[w] < bi)) { bt = swt[w]; bi = sit[w]; }
            if (swv[w] > bv || (swv[w] == bv && siv[w] < bj)) { bv = swv[w]; bj = siv[w]; }
        }
        if (bi == bj) { s_lab = bi; atomicAdd(&g_count[bi], 1.0f); }
        else          { s_lab = -1; }
    }
    __syncthreads();
    const int c = s_lab;
    if (c >= 0 && act) {   // fused scatter (rare: ~B/C rows agree)
        float* dst = g_sums + (size_t)c * C_CLS + k;
        atomicAdd(dst + 0, a.x);
        if (k + 1 < C_CLS) atomicAdd(dst + 1, a.y);
        if (k + 2 < C_CLS) atomicAdd(dst + 2, a.z);
        if (k + 3 < C_CLS) atomicAdd(dst + 3, a.w);
    }
}

__global__ void bank_kernel(const float* __restrict__ bank,
                            const float* __restrict__ alpha,
                            float* __restrict__ out_bank) {
    int i = blockIdx.x * blockDim.x + threadIdx.x;
    if (i >= C_CLS * C_CLS) return;
    int   c   = i / C_CLS;
    float a   = alpha[0];
    float cnt = g_count[c];
    float b   = bank[i];
    out_bank[i] = (cnt > 0.0f) ? (a * b + (1.0f - a) * (g_sums[i] / cnt)) : b;
}

// ---------------------------------------------------------------------------
// fp8 HMMA GEMM (NT): D[bm:+128, bn:+128] = A * B^T (residual part)
// 256 thr, 8 warps (4m x 2n), warp tile 32x64, 64-byte K chunks,
// cp.async 4-stage, loads issued BEFORE compute, ONE sync/chunk, 2 CTAs/SM
#define BM     128
#define BN     128
#define BKB    64                    // k bytes per chunk
#define STAGES 4
#define LDSPB  80                    // padded smem row stride (bytes)
#define NCH    (KPAD / BKB)          // 16
#define STA    (BM * LDSPB)          // 10240
#define STB    (BN * LDSPB)          // 10240
#define STT    (STA + STB)
#define SMEMT  (STAGES * STT)        // 81920

__global__ void __launch_bounds__(256, 2)
gemm_fp8(const float* __restrict__ p_vlm,
         float* __restrict__ out,
         int mode) {
    extern __shared__ char smem[];
    const uint32_t sb = smem_u32(smem);

    const uint8_t* __restrict__ A  = (mode == 1) ? g_Af8  : g_Ef8;
    const uint8_t* __restrict__ Bm = (mode == 1) ? g_B1f8 : g_B2f8;

    const int t   = threadIdx.x;
    const int wid = t >> 5;
    const int l   = t & 31;
    const int wm  = wid >> 1;            // 0..3 -> m offset wm*32
    const int wn  = wid & 1;             // 0..1 -> n offset wn*64
    const int bm  = blockIdx.y * BM;
    const int bn  = blockIdx.x * BN;

    const int r = t >> 2, u = t & 3;     // loader: 64 rows x 4x16B per pass

    float acc[2][8][4];
    #pragma unroll
    for (int mi = 0; mi < 2; mi++)
        #pragma unroll
        for (int ni = 0; ni < 8; ni++)
            #pragma unroll
            for (int kk = 0; kk < 4; kk++) acc[mi][ni][kk] = 0.0f;

    const int aRow = wm * 32 + (l & 15);
    const int aOff = (l & 16) ? 16 : 0;   // bytes
    const int bRow = wn * 64 + (l & 7) + ((l & 16) ? 8 : 0);
    const int bOff = (l & 8) ? 16 : 0;    // bytes

    auto load_stage = [&](int chunk, int buf) {
        const int kc = chunk * BKB;
        const uint32_t dA = sb + buf * STT;
        const uint32_t dB = dA + STA;
        #pragma unroll
        for (int i = 0; i < 2; i++) {
            int rr = r + 64 * i;
            CP16(dA + rr * LDSPB + u * 16,
                 (const void*)(A + (size_t)(bm + rr) * KPAD + kc + u * 16));
        }
        #pragma unroll
        for (int i = 0; i < 2; i++) {
            int rr = r + 64 * i;
            CP16(dB + rr * LDSPB + u * 16,
                 (const void*)(Bm + (size_t)(bn + rr) * KPAD + kc + u * 16));
        }
    };

    #pragma unroll
    for (int s = 0; s < STAGES - 1; ++s) { load_stage(s, s); CP_COMMIT(); }

    for (int c = 0; c < NCH; ++c) {
        CP_WAIT2();                      // chunk c landed (2 newer may pend)
        __syncthreads();                 // single barrier per chunk

        // issue chunk c+3 BEFORE compute (buffer (c+3)%4 = (c-1)%4, consumed
        // at iter c-1, ordered by the sync above)
        const int nc_ = c + STAGES - 1;
        if (nc_ < NCH) load_stage(nc_, nc_ % STAGES);
        CP_COMMIT();

        const int buf = c % STAGES;
        const uint32_t baseA = sb + buf * STT;
        const uint32_t baseB = baseA + STA;

        // batch ALL frag loads of the chunk, then ALL 32 MMAs
        uint32_t af[2][2][4], bf[2][4][4];
        #pragma unroll
        for (int s = 0; s < 2; ++s) {
            #pragma unroll
            for (int mi = 0; mi < 2; mi++)
                ldmx4(af[s][mi], baseA + (aRow + mi * 16) * LDSPB + s * 32 + aOff);
            #pragma unroll
            for (int g = 0; g < 4; g++)
                ldmx4(bf[s][g], baseB + (bRow + g * 16) * LDSPB + s * 32 + bOff);
        }
        #pragma unroll
        for (int s = 0; s < 2; ++s)
            #pragma unroll
            for (int mi = 0; mi < 2; mi++)
                #pragma unroll
                for (int g = 0; g < 4; g++) {
                    mma_fp8(acc[mi][2 * g],     af[s][mi], bf[s][g][0], bf[s][g][1]);
                    mma_fp8(acc[mi][2 * g + 1], af[s][mi], bf[s][g][2], bf[s][g][3]);
                }
    }

    // ---- epilogue ----
    // rows: bm + wm*32 + mi*16 + (l>>2) + h*8 ; cols: bn + wn*64 + ni*8 + (l&3)*2
    if (mode == 1) {
        #pragma unroll
        for (int mi = 0; mi < 2; mi++) {
            #pragma unroll
            for (int h = 0; h < 2; h++) {
                const int row = bm + wm * 32 + mi * 16 + (l >> 2) + h * 8;
                float rs = 0.0f;
                #pragma unroll
                for (int ni = 0; ni < 8; ni++) {
                    const int col = bn + wn * 64 + ni * 8 + (l & 3) * 2;
                    float e0 = 0.0f, e1 = 0.0f;
                    if (col < C_CLS)
                        e0 = __expf((g_m1[col] + acc[mi][ni][h * 2 + 0] * DEQ) * NORMF);
                    if (col + 1 < C_CLS)
                        e1 = __expf((g_m1[col + 1] + acc[mi][ni][h * 2 + 1] * DEQ) * NORMF);
                    *(uint16_t*)&g_Ef8[(size_t)row * KPAD + col] =
                        f2_fp8x2(e0 * SA, e1 * SA);
                    rs += e0 + e1;
                }
                rs += __shfl_xor_sync(0xFFFFFFFFu, rs, 1);
                rs += __shfl_xor_sync(0xFFFFFFFFu, rs, 2);
                if ((l & 3) == 0) atomicAdd(&g_rowsum[row], rs);
            }
        }
    } else {
        #pragma unroll
        for (int mi = 0; mi < 2; mi++) {
            #pragma unroll
            for (int h = 0; h < 2; h++) {
                const int row = bm + wm * 32 + mi * 16 + (l >> 2) + h * 8;
                const float inv = 1.0f / g_rowsum[row];
                const float* pvrow = p_vlm + (size_t)row * C_CLS;
                float*       orow  = out   + (size_t)row * C_CLS;
                #pragma unroll
                for (int ni = 0; ni < 8; ni++) {
                    const int col = bn + wn * 64 + ni * 8 + (l & 3) * 2;
                    #pragma unroll
                    for (int e = 0; e < 2; e++) {
                        int n = col + e;
                        if (n < C_CLS) {
                            float pt  = g_m2[n] * INV_C
                                      + acc[mi][ni][h * 2 + e] * DEQ * inv;
                            float pv  = __ldg(pvrow + n);
                            float eut = __expf(pt * __logf(pt + EPSU));
                            float euv = __expf(pv * __logf(pv + EPSU));
                            orow[n] = (eut * pt + euv * pv) / (eut + euv);
                        }
                    }
                }
            }
        }
    }
}

// ---------------------------------------------------------------------------
extern "C" void kernel_launch(void* const* d_in, const int* in_sizes, int n_in,
                              void* d_out, int out_size) {
    const float* p_tar = (const float*)d_in[0];
    const float* p_vlm = (const float*)d_in[1];
    const float* alpha = (const float*)d_in[2];
    const float* bank  = (const float*)d_in[3];
    float* out      = (float*)d_out;                       // p_mix [B,C]
    float* out_bank = out + (size_t)B_ROWS * C_CLS;        // bank_new [C,C]

    static int attr_set = 0;
    if (!attr_set) {
        cudaFuncSetAttribute(gemm_fp8, cudaFuncAttributeMaxDynamicSharedMemorySize,
                             SMEMT);
        attr_set = 1;
    }

    dim3 gg(KPAD / BN, B_ROWS / BM);  // (8, 256)

    zero_kernel<<<(C_CLS * C_CLS + 255) / 256, 256>>>();          // 1
    convB1_kernel<<<KPAD, 128>>>(bank);                           // 2
    prep_kernel<<<B_ROWS, 256>>>(p_tar, p_vlm);                   // 3
    gemm_fp8<<<gg, 256, SMEMT>>>(nullptr, nullptr, 1);            // 4 <- ncu capture
    transT_kernel<<<dim3(32, 32), 256>>>(bank);                   // 5
    convB2_kernel<<<KPAD, 128>>>();                               // 6
    gemm_fp8<<<gg, 256, SMEMT>>>(p_vlm, out, 2);                  // 7
    bank_kernel<<<(C_CLS * C_CLS + 255) / 256, 256>>>(bank, alpha, out_bank); // 8
}

// round 10
// speedup vs baseline: 1.2296x; 1.0252x over previous
#include <cuda_runtime.h>
#include <cuda_bf16.h>
#include <cuda_fp8.h>
#include <cstdint>
#include <math.h>

#define B_ROWS 32768
#define C_CLS  1000
#define KPAD   1024
#define EPSU   1e-6f
#define NORMF  0.031622776601683794f   // 1/sqrt(1000)
#define INV_C  0.001f
#define SA     128.0f                  // fp8 scale for A / E
#define SB     256.0f                  // fp8 scale for centered B residuals
#define DEQ    (1.0f / (128.0f * 256.0f))

// ---------------- scratch (__device__ globals; no allocations) --------------
__device__ uint8_t g_Af8[(size_t)B_ROWS * KPAD];   // p_tar  fp8 x128, padded
__device__ uint8_t g_Ef8[(size_t)B_ROWS * KPAD];   // E      fp8 x128, padded
__device__ uint8_t g_B1f8[(size_t)KPAD * KPAD];    // (bank - m1) x256  [n][k]
__device__ uint8_t g_B2f8[(size_t)KPAD * KPAD];    // (bank^T - m2) x256 [j][k]
__device__ float   g_BT[(size_t)KPAD * KPAD];      // bank^T fp32 staging
__device__ float   g_m1[KPAD];                     // row means of bank
__device__ float   g_m2[KPAD];                     // raw col sums of bank
__device__ float   g_rowsum[B_ROWS];
__device__ float   g_sums[(size_t)C_CLS * C_CLS];
__device__ float   g_count[C_CLS];

// ---------------- helpers ----------------------------------------------------
__device__ __forceinline__ uint16_t f2_fp8x2(float lo, float hi) {
    __nv_fp8x2_storage_t r =
        __nv_cvt_float2_to_fp8x2(make_float2(lo, hi), __NV_SATFINITE, __NV_E4M3);
    return (uint16_t)r;
}
__device__ __forceinline__ uint32_t smem_u32(const void* p) {
    uint32_t a;
    asm("{ .reg .u64 t; cvta.to.shared.u64 t, %1; cvt.u32.u64 %0, t; }"
        : "=r"(a) : "l"(p));
    return a;
}
__device__ __forceinline__ void ldmx4(uint32_t* r, uint32_t addr) {
    asm volatile("ldmatrix.sync.aligned.m8n8.x4.shared.b16 {%0,%1,%2,%3}, [%4];"
                 : "=r"(r[0]), "=r"(r[1]), "=r"(r[2]), "=r"(r[3]) : "r"(addr));
}
__device__ __forceinline__ void mma_fp8(float* c, const uint32_t* a,
                                        uint32_t b0, uint32_t b1) {
    asm volatile("mma.sync.aligned.m16n8k32.row.col.f32.e4m3.e4m3.f32 "
                 "{%0,%1,%2,%3}, {%4,%5,%6,%7}, {%8,%9}, {%0,%1,%2,%3};"
                 : "+f"(c[0]), "+f"(c[1]), "+f"(c[2]), "+f"(c[3])
                 : "r"(a[0]), "r"(a[1]), "r"(a[2]), "r"(a[3]), "r"(b0), "r"(b1));
}
#define CP16(dst, src) \
    asm volatile("cp.async.cg.shared.global [%0], [%1], 16;" :: "r"(dst), "l"(src))
#define CP_COMMIT() asm volatile("cp.async.commit_group;")
#define CP_WAIT1()  asm volatile("cp.async.wait_group 1;")

// ---------------------------------------------------------------------------
__global__ void zero_kernel() {
    int i = blockIdx.x * blockDim.x + threadIdx.x;
    if (i < C_CLS * C_CLS) g_sums[i] = 0.0f;
    if (i < B_ROWS)        g_rowsum[i] = 0.0f;
    if (i < C_CLS)         g_count[i] = 0.0f;
    if (i < KPAD)          g_m2[i] = 0.0f;
}

// B1: row means + centered fp8 residual rows of bank  [n][k]
__global__ void __launch_bounds__(128) convB1_kernel(const float* __restrict__ bank) {
    const int n = blockIdx.x;     // 0..1023
    const int t = threadIdx.x;
    uint32_t* dst = reinterpret_cast<uint32_t*>(g_B1f8 + (size_t)n * KPAD);
    if (n >= C_CLS) {
        for (int u = t; u < KPAD / 4; u += 128) dst[u] = 0u;
        if (t == 0) g_m1[n] = 0.0f;
        return;
    }
    const float* row = bank + (size_t)n * C_CLS;
    float s = 0.0f;
    for (int k = t; k < C_CLS; k += 128) s += row[k];
    #pragma unroll
    for (int o = 16; o > 0; o >>= 1) s += __shfl_xor_sync(0xFFFFFFFFu, s, o);
    __shared__ float sw[4];
    if ((t & 31) == 0) sw[t >> 5] = s;
    __syncthreads();
    const float m = (sw[0] + sw[1] + sw[2] + sw[3]) * INV_C;
    if (t == 0) g_m1[n] = m;
    for (int u = t; u < KPAD / 4; u += 128) {
        int k = 4 * u;
        float4 v = make_float4(0.f, 0.f, 0.f, 0.f);
        if (k + 3 < C_CLS) v = *(const float4*)(row + k);  // C_CLS % 4 == 0
        uint16_t lo = f2_fp8x2((k < C_CLS) ? (v.x - m) * SB : 0.f,
                               (k < C_CLS) ? (v.y - m) * SB : 0.f);
        uint16_t hi = f2_fp8x2((k < C_CLS) ? (v.z - m) * SB : 0.f,
                               (k < C_CLS) ? (v.w - m) * SB : 0.f);
        dst[u] = (uint32_t)lo | ((uint32_t)hi << 16);
    }
}

// T1: tiled transpose bank -> g_BT (fp32) + column-sum atomics into g_m2
__global__ void __launch_bounds__(256) transT_kernel(const float* __restrict__ bank) {
    __shared__ float tile[32][33];
    const int tk = blockIdx.y * 32;
    const int tj = blockIdx.x * 32;
    const int jx = threadIdx.x & 31;
    const int ky = threadIdx.x >> 5;
    #pragma unroll
    for (int s = 0; s < 4; s++) {
        int k = tk + ky + s * 8, j = tj + jx;
        tile[ky + s * 8][jx] = (k < C_CLS && j < C_CLS)
                             ? bank[(size_t)k * C_CLS + j] : 0.0f;
    }
    __syncthreads();
    #pragma unroll
    for (int s = 0; s < 4; s++) {
        int j = tj + ky + s * 8, k = tk + jx;
        g_BT[(size_t)j * KPAD + k] = tile[jx][ky + s * 8];
    }
    float ps = 0.0f;
    #pragma unroll
    for (int s = 0; s < 4; s++) ps += tile[ky + s * 8][jx];
    __syncthreads();
    tile[ky][jx] = ps;
    __syncthreads();
    if (ky == 0) {
        float tot = 0.0f;
        #pragma unroll
        for (int y = 0; y < 8; y++) tot += tile[y][jx];
        if (tj + jx < C_CLS) atomicAdd(&g_m2[tj + jx], tot);
    }
}

// T2: centered fp8 residual rows of bank^T  [j][k]
__global__ void __launch_bounds__(128) convB2_kernel() {
    const int j = blockIdx.x;
    const int t = threadIdx.x;
    uint32_t* dst = reinterpret_cast<uint32_t*>(g_B2f8 + (size_t)j * KPAD);
    if (j >= C_CLS) {
        for (int u = t; u < KPAD / 4; u += 128) dst[u] = 0u;
        return;
    }
    const float m = g_m2[j] * INV_C;
    const float* row = g_BT + (size_t)j * KPAD;
    for (int u = t; u < KPAD / 4; u += 128) {
        int k = 4 * u;
        if (k + 3 < C_CLS) {
            float4 v = *(const float4*)(row + k);
            uint16_t lo = f2_fp8x2((v.x - m) * SB, (v.y - m) * SB);
            uint16_t hi = f2_fp8x2((v.z - m) * SB, (v.w - m) * SB);
            dst[u] = (uint32_t)lo | ((uint32_t)hi << 16);
        } else {
            dst[u] = 0u;
        }
    }
}

// prep: p_tar -> fp8 (g_Af8) + dual argmax + agreement + fused scatter-add
__global__ void __launch_bounds__(256) prep_kernel(const float* __restrict__ p_tar,
                                                   const float* __restrict__ p_vlm) {
    const int row = blockIdx.x;
    const int t   = threadIdx.x;
    const float4* pt4 = reinterpret_cast<const float4*>(p_tar + (size_t)row * C_CLS);
    const float4* pv4 = reinterpret_cast<const float4*>(p_vlm + (size_t)row * C_CLS);
    uint32_t* arow = reinterpret_cast<uint32_t*>(g_Af8 + (size_t)row * KPAD);

    float vt = -1.0f, vv = -1.0f;
    int   it = 0,     iv = 0;
    float4 a = make_float4(0.f, 0.f, 0.f, 0.f);
    const int k = 4 * t;
    const bool act = (t < KPAD / 4) && (k < C_CLS);
    if (act) {
        a = pt4[t];
        float4 b = pv4[t];
        if (a.x > vt) { vt = a.x; it = k; }
        if (a.y > vt) { vt = a.y; it = k + 1; }
        if (a.z > vt) { vt = a.z; it = k + 2; }
        if (a.w > vt) { vt = a.w; it = k + 3; }
        if (b.x > vv) { vv = b.x; iv = k; }
        if (b.y > vv) { vv = b.y; iv = k + 1; }
        if (b.z > vv) { vv = b.z; iv = k + 2; }
        if (b.w > vv) { vv = b.w; iv = k + 3; }
        uint16_t lo = f2_fp8x2(a.x * SA, a.y * SA);
        uint16_t hi = f2_fp8x2(a.z * SA, a.w * SA);
        arow[t] = (uint32_t)lo | ((uint32_t)hi << 16);
    } else if (t < KPAD / 4) {
        arow[t] = 0u;
    }
    const int lane = t & 31;
    #pragma unroll
    for (int off = 16; off > 0; off >>= 1) {
        float ov = __shfl_down_sync(0xFFFFFFFFu, vt, off);
        int   oi = __shfl_down_sync(0xFFFFFFFFu, it, off);
        if (ov > vt || (ov == vt && oi < it)) { vt = ov; it = oi; }
        ov = __shfl_down_sync(0xFFFFFFFFu, vv, off);
        oi = __shfl_down_sync(0xFFFFFFFFu, iv, off);
        if (ov > vv || (ov == vv && oi < iv)) { vv = ov; iv = oi; }
    }
    __shared__ float swt[8], swv[8];
    __shared__ int   sit[8], siv[8];
    __shared__ int   s_lab;
    if (lane == 0) { swt[t >> 5] = vt; sit[t >> 5] = it; swv[t >> 5] = vv; siv[t >> 5] = iv; }
    __syncthreads();
    if (t == 0) {
        float bt = swt[0], bv = swv[0];
        int   bi = sit[0], bj = siv[0];
        #pragma unroll
        for (int w = 1; w < 8; w++) {
            if (swt[w] > bt || (swt[w] == bt && sit[w] < bi)) { bt = swt[w]; bi = sit[w]; }
            if (swv[w] > bv || (swv[w] == bv && siv[w] < bj)) { bv = swv[w]; bj = siv[w]; }
        }
        if (bi == bj) { s_lab = bi; atomicAdd(&g_count[bi], 1.0f); }
        else          { s_lab = -1; }
    }
    __syncthreads();
    const int c = s_lab;
    if (c >= 0 && act) {   // fused scatter (rare: ~B/C rows agree)
        float* dst = g_sums + (size_t)c * C_CLS + k;
        atomicAdd(dst + 0, a.x);
        if (k + 1 < C_CLS) atomicAdd(dst + 1, a.y);
        if (k + 2 < C_CLS) atomicAdd(dst + 2, a.z);
        if (k + 3 < C_CLS) atomicAdd(dst + 3, a.w);
    }
}

__global__ void bank_kernel(const float* __restrict__ bank,
                            const float* __restrict__ alpha,
                            float* __restrict__ out_bank) {
    int i = blockIdx.x * blockDim.x + threadIdx.x;
    if (i >= C_CLS * C_CLS) return;
    int   c   = i / C_CLS;
    float a   = alpha[0];
    float cnt = g_count[c];
    float b   = bank[i];
    out_bank[i] = (cnt > 0.0f) ? (a * b + (1.0f - a) * (g_sums[i] / cnt)) : b;
}

// ---------------------------------------------------------------------------
// fp8 HMMA GEMM (NT): D[bm:+128, bn:+64] = A * B^T (residual part)
// 128 thr, 4 warps (4m x 1n), warp tile 32x64, 64-byte K chunks,
// cp.async 3-stage, loads before compute, ONE sync/chunk, 4 CTAs/SM
#define BM     128
#define BN     64
#define BKB    64                    // k bytes per chunk
#define STAGES 3
#define LDSPB  80                    // padded smem row stride (bytes)
#define NCH    (KPAD / BKB)          // 16
#define STA    (BM * LDSPB)          // 10240
#define STB    (BN * LDSPB)          // 5120
#define STT    (STA + STB)           // 15360
#define SMEMT  (STAGES * STT)        // 46080

__global__ void __launch_bounds__(128, 4)
gemm_fp8(const float* __restrict__ p_vlm,
         float* __restrict__ out,
         int mode) {
    extern __shared__ char smem[];
    const uint32_t sb = smem_u32(smem);

    const uint8_t* __restrict__ A  = (mode == 1) ? g_Af8  : g_Ef8;
    const uint8_t* __restrict__ Bm = (mode == 1) ? g_B1f8 : g_B2f8;

    const int t   = threadIdx.x;
    const int wid = t >> 5;              // 0..3 -> m offset wid*32
    const int l   = t & 31;
    const int bm  = blockIdx.y * BM;
    const int bn  = blockIdx.x * BN;

    const int r = t >> 2, u = t & 3;     // loader: 32 rows x 4x16B per pass

    float acc[2][8][4];
    #pragma unroll
    for (int mi = 0; mi < 2; mi++)
        #pragma unroll
        for (int ni = 0; ni < 8; ni++)
            #pragma unroll
            for (int kk = 0; kk < 4; kk++) acc[mi][ni][kk] = 0.0f;

    const int aRow = wid * 32 + (l & 15);
    const int aOff = (l & 16) ? 16 : 0;   // bytes
    const int bRow = (l & 7) + ((l & 16) ? 8 : 0);
    const int bOff = (l & 8) ? 16 : 0;    // bytes

    auto load_stage = [&](int chunk, int buf) {
        const int kc = chunk * BKB;
        const uint32_t dA = sb + buf * STT;
        const uint32_t dB = dA + STA;
        #pragma unroll
        for (int i = 0; i < 4; i++) {     // A: 128 rows
            int rr = r + 32 * i;
            CP16(dA + rr * LDSPB + u * 16,
                 (const void*)(A + (size_t)(bm + rr) * KPAD + kc + u * 16));
        }
        #pragma unroll
        for (int i = 0; i < 2; i++) {     // B: 64 rows
            int rr = r + 32 * i;
            CP16(dB + rr * LDSPB + u * 16,
                 (const void*)(Bm + (size_t)(bn + rr) * KPAD + kc + u * 16));
        }
    };

    #pragma unroll
    for (int s = 0; s < STAGES - 1; ++s) { load_stage(s, s); CP_COMMIT(); }

    for (int c = 0; c < NCH; ++c) {
        CP_WAIT1();                      // chunk c landed (1 newer may pend)
        __syncthreads();                 // single barrier per chunk

        // issue chunk c+2 BEFORE compute (buf (c+2)%3 = (c-1)%3, consumed in
        // iter c-1, ordered by the sync above)
        const int nc_ = c + STAGES - 1;
        if (nc_ < NCH) load_stage(nc_, nc_ % STAGES);
        CP_COMMIT();

        const int buf = c % STAGES;
        const uint32_t baseA = sb + buf * STT;
        const uint32_t baseB = baseA + STA;

        #pragma unroll
        for (int s = 0; s < 2; ++s) {    // two k32 steps (interleaved frags)
            uint32_t af[2][4];
            #pragma unroll
            for (int mi = 0; mi < 2; mi++)
                ldmx4(af[mi], baseA + (aRow + mi * 16) * LDSPB + s * 32 + aOff);
            uint32_t bf[4][4];
            #pragma unroll
            for (int g = 0; g < 4; g++)
                ldmx4(bf[g], baseB + (bRow + g * 16) * LDSPB + s * 32 + bOff);
            #pragma unroll
            for (int mi = 0; mi < 2; mi++)
                #pragma unroll
                for (int g = 0; g < 4; g++) {
                    mma_fp8(acc[mi][2 * g],     af[mi], bf[g][0], bf[g][1]);
                    mma_fp8(acc[mi][2 * g + 1], af[mi], bf[g][2], bf[g][3]);
                }
        }
    }

    // ---- epilogue ----
    // rows: bm + wid*32 + mi*16 + (l>>2) + h*8 ; cols: bn + ni*8 + (l&3)*2
    if (mode == 1) {
        #pragma unroll
        for (int mi = 0; mi < 2; mi++) {
            #pragma unroll
            for (int h = 0; h < 2; h++) {
                const int row = bm + wid * 32 + mi * 16 + (l >> 2) + h * 8;
                float rs = 0.0f;
                #pragma unroll
                for (int ni = 0; ni < 8; ni++) {
                    const int col = bn + ni * 8 + (l & 3) * 2;
                    float e0 = 0.0f, e1 = 0.0f;
                    if (col < C_CLS)
                        e0 = __expf((g_m1[col] + acc[mi][ni][h * 2 + 0] * DEQ) * NORMF);
                    if (col + 1 < C_CLS)
                        e1 = __expf((g_m1[col + 1] + acc[mi][ni][h * 2 + 1] * DEQ) * NORMF);
                    *(uint16_t*)&g_Ef8[(size_t)row * KPAD + col] =
                        f2_fp8x2(e0 * SA, e1 * SA);
                    rs += e0 + e1;
                }
                rs += __shfl_xor_sync(0xFFFFFFFFu, rs, 1);
                rs += __shfl_xor_sync(0xFFFFFFFFu, rs, 2);
                if ((l & 3) == 0) atomicAdd(&g_rowsum[row], rs);
            }
        }
    } else {
        #pragma unroll
        for (int mi = 0; mi < 2; mi++) {
            #pragma unroll
            for (int h = 0; h < 2; h++) {
                const int row = bm + wid * 32 + mi * 16 + (l >> 2) + h * 8;
                const float inv = 1.0f / g_rowsum[row];
                const float* pvrow = p_vlm + (size_t)row * C_CLS;
                float*       orow  = out   + (size_t)row * C_CLS;
                #pragma unroll
                for (int ni = 0; ni < 8; ni++) {
                    const int col = bn + ni * 8 + (l & 3) * 2;
                    #pragma unroll
                    for (int e = 0; e < 2; e++) {
                        int n = col + e;
                        if (n < C_CLS) {
                            float pt  = g_m2[n] * INV_C
                                      + acc[mi][ni][h * 2 + e] * DEQ * inv;
                            float pv  = __ldg(pvrow + n);
                            float eut = __expf(pt * __logf(pt + EPSU));
                            float euv = __expf(pv * __logf(pv + EPSU));
                            orow[n] = (eut * pt + euv * pv) / (eut + euv);
                        }
                    }
                }
            }
        }
    }
}

// ---------------------------------------------------------------------------
extern "C" void kernel_launch(void* const* d_in, const int* in_sizes, int n_in,
                              void* d_out, int out_size) {
    const float* p_tar = (const float*)d_in[0];
    const float* p_vlm = (const float*)d_in[1];
    const float* alpha = (const float*)d_in[2];
    const float* bank  = (const float*)d_in[3];
    float* out      = (float*)d_out;                       // p_mix [B,C]
    float* out_bank = out + (size_t)B_ROWS * C_CLS;        // bank_new [C,C]

    static int attr_set = 0;
    if (!attr_set) {
        cudaFuncSetAttribute(gemm_fp8, cudaFuncAttributeMaxDynamicSharedMemorySize,
                             SMEMT);
        attr_set = 1;
    }

    dim3 gg(KPAD / BN, B_ROWS / BM);  // (16, 256)

    zero_kernel<<<(C_CLS * C_CLS + 255) / 256, 256>>>();          // 1
    convB1_kernel<<<KPAD, 128>>>(bank);                           // 2
    prep_kernel<<<B_ROWS, 256>>>(p_tar, p_vlm);                   // 3
    gemm_fp8<<<gg, 128, SMEMT>>>(nullptr, nullptr, 1);            // 4 <- ncu capture
    transT_kernel<<<dim3(32, 32), 256>>>(bank);                   // 5
    convB2_kernel<<<KPAD, 128>>>();                               // 6
    gemm_fp8<<<gg, 128, SMEMT>>>(p_vlm, out, 2);                  // 7
    bank_kernel<<<(C_CLS * C_CLS + 255) / 256, 256>>>(bank, alpha, out_bank); // 8
}

// round 11
// speedup vs baseline: 2.4642x; 2.0041x over previous
#include <cuda_runtime.h>
#include <cuda_bf16.h>
#include <cuda_fp8.h>
#include <cstdint>
#include <math.h>

#define B_ROWS 32768
#define C_CLS  1000
#define KPAD   1024
#define EPSU   1e-6f
#define NORMF  0.031622776601683794f   // 1/sqrt(1000)
#define INV_C  0.001f
#define SA     128.0f                  // fp8 scale for A / E
#define SB     256.0f                  // fp8 scale for centered B residuals
#define DEQ    (1.0f / (128.0f * 256.0f))

// ---------------- scratch (__device__ globals; no allocations) --------------
__device__ uint8_t g_Af8[(size_t)B_ROWS * KPAD];   // p_tar  fp8 x128, padded
__device__ uint8_t g_Ef8[(size_t)B_ROWS * KPAD];   // E      fp8 x128, padded
__device__ uint8_t g_B1f8[(size_t)KPAD * KPAD];    // (bank - m1) x256  [n][k]
__device__ uint8_t g_B2f8[(size_t)KPAD * KPAD];    // (bank^T - m2) x256 [j][k]
__device__ float   g_BT[(size_t)KPAD * KPAD];      // bank^T fp32 staging
__device__ float   g_m1[KPAD];                     // row means of bank
__device__ float   g_m2[KPAD];                     // raw col sums of bank
__device__ float   g_rowsum[B_ROWS];
__device__ float   g_sums[(size_t)C_CLS * C_CLS];
__device__ float   g_count[C_CLS];
__device__ int     g_nzB1;                         // residual B1 has nonzero?
__device__ int     g_nzB2;                         // residual B2 has nonzero?

// ---------------- helpers ----------------------------------------------------
__device__ __forceinline__ uint16_t f2_fp8x2(float lo, float hi) {
    __nv_fp8x2_storage_t r =
        __nv_cvt_float2_to_fp8x2(make_float2(lo, hi), __NV_SATFINITE, __NV_E4M3);
    return (uint16_t)r;
}
__device__ __forceinline__ uint32_t smem_u32(const void* p) {
    uint32_t a;
    asm("{ .reg .u64 t; cvta.to.shared.u64 t, %1; cvt.u32.u64 %0, t; }"
        : "=r"(a) : "l"(p));
    return a;
}
__device__ __forceinline__ void ldmx4(uint32_t* r, uint32_t addr) {
    asm volatile("ldmatrix.sync.aligned.m8n8.x4.shared.b16 {%0,%1,%2,%3}, [%4];"
                 : "=r"(r[0]), "=r"(r[1]), "=r"(r[2]), "=r"(r[3]) : "r"(addr));
}
__device__ __forceinline__ void mma_fp8(float* c, const uint32_t* a,
                                        uint32_t b0, uint32_t b1) {
    asm volatile("mma.sync.aligned.m16n8k32.row.col.f32.e4m3.e4m3.f32 "
                 "{%0,%1,%2,%3}, {%4,%5,%6,%7}, {%8,%9}, {%0,%1,%2,%3};"
                 : "+f"(c[0]), "+f"(c[1]), "+f"(c[2]), "+f"(c[3])
                 : "r"(a[0]), "r"(a[1]), "r"(a[2]), "r"(a[3]), "r"(b0), "r"(b1));
}
#define CP16(dst, src) \
    asm volatile("cp.async.cg.shared.global [%0], [%1], 16;" :: "r"(dst), "l"(src))
#define CP_COMMIT() asm volatile("cp.async.commit_group;")
#define CP_WAIT1()  asm volatile("cp.async.wait_group 1;")

// ---------------------------------------------------------------------------
__global__ void zero_kernel() {
    int i = blockIdx.x * blockDim.x + threadIdx.x;
    if (i < C_CLS * C_CLS) g_sums[i] = 0.0f;
    if (i < B_ROWS)        g_rowsum[i] = 0.0f;
    if (i < C_CLS)         g_count[i] = 0.0f;
    if (i < KPAD)          g_m2[i] = 0.0f;
    if (i == 0) { g_nzB1 = 0; g_nzB2 = 0; }
}

// B1: row means + centered fp8 residual rows of bank [n][k] + nonzero flag
__global__ void __launch_bounds__(128) convB1_kernel(const float* __restrict__ bank) {
    const int n = blockIdx.x;     // 0..1023
    const int t = threadIdx.x;
    uint32_t* dst = reinterpret_cast<uint32_t*>(g_B1f8 + (size_t)n * KPAD);
    if (n >= C_CLS) {
        for (int u = t; u < KPAD / 4; u += 128) dst[u] = 0u;
        if (t == 0) g_m1[n] = 0.0f;
        return;
    }
    const float* row = bank + (size_t)n * C_CLS;
    float s = 0.0f;
    for (int k = t; k < C_CLS; k += 128) s += row[k];
    #pragma unroll
    for (int o = 16; o > 0; o >>= 1) s += __shfl_xor_sync(0xFFFFFFFFu, s, o);
    __shared__ float sw[4];
    if ((t & 31) == 0) sw[t >> 5] = s;
    __syncthreads();
    const float m = (sw[0] + sw[1] + sw[2] + sw[3]) * INV_C;
    if (t == 0) g_m1[n] = m;
    uint32_t nz = 0u;
    for (int u = t; u < KPAD / 4; u += 128) {
        int k = 4 * u;
        float4 v = make_float4(0.f, 0.f, 0.f, 0.f);
        if (k + 3 < C_CLS) v = *(const float4*)(row + k);  // C_CLS % 4 == 0
        uint16_t lo = f2_fp8x2((k < C_CLS) ? (v.x - m) * SB : 0.f,
                               (k < C_CLS) ? (v.y - m) * SB : 0.f);
        uint16_t hi = f2_fp8x2((k < C_CLS) ? (v.z - m) * SB : 0.f,
                               (k < C_CLS) ? (v.w - m) * SB : 0.f);
        uint32_t packed = (uint32_t)lo | ((uint32_t)hi << 16);
        dst[u] = packed;
        nz |= (packed & 0x7F7F7F7Fu);   // value-zero test (ignore sign of -0)
    }
    if (nz) atomicOr(&g_nzB1, 1);
}

// T1: tiled transpose bank -> g_BT (fp32) + column-sum atomics into g_m2
__global__ void __launch_bounds__(256) transT_kernel(const float* __restrict__ bank) {
    __shared__ float tile[32][33];
    const int tk = blockIdx.y * 32;
    const int tj = blockIdx.x * 32;
    const int jx = threadIdx.x & 31;
    const int ky = threadIdx.x >> 5;
    #pragma unroll
    for (int s = 0; s < 4; s++) {
        int k = tk + ky + s * 8, j = tj + jx;
        tile[ky + s * 8][jx] = (k < C_CLS && j < C_CLS)
                             ? bank[(size_t)k * C_CLS + j] : 0.0f;
    }
    __syncthreads();
    #pragma unroll
    for (int s = 0; s < 4; s++) {
        int j = tj + ky + s * 8, k = tk + jx;
        g_BT[(size_t)j * KPAD + k] = tile[jx][ky + s * 8];
    }
    float ps = 0.0f;
    #pragma unroll
    for (int s = 0; s < 4; s++) ps += tile[ky + s * 8][jx];
    __syncthreads();
    tile[ky][jx] = ps;
    __syncthreads();
    if (ky == 0) {
        float tot = 0.0f;
        #pragma unroll
        for (int y = 0; y < 8; y++) tot += tile[y][jx];
        if (tj + jx < C_CLS) atomicAdd(&g_m2[tj + jx], tot);
    }
}

// T2: centered fp8 residual rows of bank^T [j][k] + nonzero flag
__global__ void __launch_bounds__(128) convB2_kernel() {
    const int j = blockIdx.x;
    const int t = threadIdx.x;
    uint32_t* dst = reinterpret_cast<uint32_t*>(g_B2f8 + (size_t)j * KPAD);
    if (j >= C_CLS) {
        for (int u = t; u < KPAD / 4; u += 128) dst[u] = 0u;
        return;
    }
    const float m = g_m2[j] * INV_C;
    const float* row = g_BT + (size_t)j * KPAD;
    uint32_t nz = 0u;
    for (int u = t; u < KPAD / 4; u += 128) {
        int k = 4 * u;
        if (k + 3 < C_CLS) {
            float4 v = *(const float4*)(row + k);
            uint16_t lo = f2_fp8x2((v.x - m) * SB, (v.y - m) * SB);
            uint16_t hi = f2_fp8x2((v.z - m) * SB, (v.w - m) * SB);
            uint32_t packed = (uint32_t)lo | ((uint32_t)hi << 16);
            dst[u] = packed;
            nz |= (packed & 0x7F7F7F7Fu);
        } else {
            dst[u] = 0u;
        }
    }
    if (nz) atomicOr(&g_nzB2, 1);
}

// prep: p_tar -> fp8 (g_Af8) + dual argmax + agreement + fused scatter-add
__global__ void __launch_bounds__(256) prep_kernel(const float* __restrict__ p_tar,
                                                   const float* __restrict__ p_vlm) {
    const int row = blockIdx.x;
    const int t   = threadIdx.x;
    const float4* pt4 = reinterpret_cast<const float4*>(p_tar + (size_t)row * C_CLS);
    const float4* pv4 = reinterpret_cast<const float4*>(p_vlm + (size_t)row * C_CLS);
    uint32_t* arow = reinterpret_cast<uint32_t*>(g_Af8 + (size_t)row * KPAD);

    float vt = -1.0f, vv = -1.0f;
    int   it = 0,     iv = 0;
    float4 a = make_float4(0.f, 0.f, 0.f, 0.f);
    const int k = 4 * t;
    const bool act = (t < KPAD / 4) && (k < C_CLS);
    if (act) {
        a = pt4[t];
        float4 b = pv4[t];
        if (a.x > vt) { vt = a.x; it = k; }
        if (a.y > vt) { vt = a.y; it = k + 1; }
        if (a.z > vt) { vt = a.z; it = k + 2; }
        if (a.w > vt) { vt = a.w; it = k + 3; }
        if (b.x > vv) { vv = b.x; iv = k; }
        if (b.y > vv) { vv = b.y; iv = k + 1; }
        if (b.z > vv) { vv = b.z; iv = k + 2; }
        if (b.w > vv) { vv = b.w; iv = k + 3; }
        uint16_t lo = f2_fp8x2(a.x * SA, a.y * SA);
        uint16_t hi = f2_fp8x2(a.z * SA, a.w * SA);
        arow[t] = (uint32_t)lo | ((uint32_t)hi << 16);
    } else if (t < KPAD / 4) {
        arow[t] = 0u;
    }
    const int lane = t & 31;
    #pragma unroll
    for (int off = 16; off > 0; off >>= 1) {
        float ov = __shfl_down_sync(0xFFFFFFFFu, vt, off);
        int   oi = __shfl_down_sync(0xFFFFFFFFu, it, off);
        if (ov > vt || (ov == vt && oi < it)) { vt = ov; it = oi; }
        ov = __shfl_down_sync(0xFFFFFFFFu, vv, off);
        oi = __shfl_down_sync(0xFFFFFFFFu, iv, off);
        if (ov > vv || (ov == vv && oi < iv)) { vv = ov; iv = oi; }
    }
    __shared__ float swt[8], swv[8];
    __shared__ int   sit[8], siv[8];
    __shared__ int   s_lab;
    if (lane == 0) { swt[t >> 5] = vt; sit[t >> 5] = it; swv[t >> 5] = vv; siv[t >> 5] = iv; }
    __syncthreads();
    if (t == 0) {
        float bt = swt[0], bv = swv[0];
        int   bi = sit[0], bj = siv[0];
        #pragma unroll
        for (int w = 1; w < 8; w++) {
            if (swt[w] > bt || (swt[w] == bt && sit[w] < bi)) { bt = swt[w]; bi = sit[w]; }
            if (swv[w] > bv || (swv[w] == bv && siv[w] < bj)) { bv = swv[w]; bj = siv[w]; }
        }
        if (bi == bj) { s_lab = bi; atomicAdd(&g_count[bi], 1.0f); }
        else          { s_lab = -1; }
    }
    __syncthreads();
    const int c = s_lab;
    if (c >= 0 && act) {   // fused scatter (rare: ~B/C rows agree)
        float* dst = g_sums + (size_t)c * C_CLS + k;
        atomicAdd(dst + 0, a.x);
        if (k + 1 < C_CLS) atomicAdd(dst + 1, a.y);
        if (k + 2 < C_CLS) atomicAdd(dst + 2, a.z);
        if (k + 3 < C_CLS) atomicAdd(dst + 3, a.w);
    }
}

__global__ void bank_kernel(const float* __restrict__ bank,
                            const float* __restrict__ alpha,
                            float* __restrict__ out_bank) {
    int i = blockIdx.x * blockDim.x + threadIdx.x;
    if (i >= C_CLS * C_CLS) return;
    int   c   = i / C_CLS;
    float a   = alpha[0];
    float cnt = g_count[c];
    float b   = bank[i];
    out_bank[i] = (cnt > 0.0f) ? (a * b + (1.0f - a) * (g_sums[i] / cnt)) : b;
}

// ---------------------------------------------------------------------------
// fp8 HMMA GEMM (NT): D[bm:+128, bn:+64] = A * B^T (residual part)
// 128 thr, 4 warps (4m x 1n), warp tile 32x64, 64-byte K chunks,
// cp.async 3-stage, ONE sync/chunk, 4 CTAs/SM.
// FAST PATH: if the residual B is value-zero (g_nzB* == 0), the mainloop is
// skipped entirely — acc stays 0.0, bit-identical to MMA on (+/-)0 operands.
#define BM     128
#define BN     64
#define BKB    64                    // k bytes per chunk
#define STAGES 3
#define LDSPB  80                    // padded smem row stride (bytes)
#define NCH    (KPAD / BKB)          // 16
#define STA    (BM * LDSPB)          // 10240
#define STB    (BN * LDSPB)          // 5120
#define STT    (STA + STB)           // 15360
#define SMEMT  (STAGES * STT)        // 46080

__global__ void __launch_bounds__(128, 4)
gemm_fp8(const float* __restrict__ p_vlm,
         float* __restrict__ out,
         int mode) {
    extern __shared__ char smem[];
    const uint32_t sb = smem_u32(smem);

    const uint8_t* __restrict__ A  = (mode == 1) ? g_Af8  : g_Ef8;
    const uint8_t* __restrict__ Bm = (mode == 1) ? g_B1f8 : g_B2f8;
    const int nzB = (mode == 1) ? g_nzB1 : g_nzB2;

    const int t   = threadIdx.x;
    const int wid = t >> 5;              // 0..3 -> m offset wid*32
    const int l   = t & 31;
    const int bm  = blockIdx.y * BM;
    const int bn  = blockIdx.x * BN;

    const int r = t >> 2, u = t & 3;     // loader: 32 rows x 4x16B per pass

    float acc[2][8][4];
    #pragma unroll
    for (int mi = 0; mi < 2; mi++)
        #pragma unroll
        for (int ni = 0; ni < 8; ni++)
            #pragma unroll
            for (int kk = 0; kk < 4; kk++) acc[mi][ni][kk] = 0.0f;

    if (nzB) {   // residual GEMM only when B residual is not value-zero
        const int aRow = wid * 32 + (l & 15);
        const int aOff = (l & 16) ? 16 : 0;   // bytes
        const int bRow = (l & 7) + ((l & 16) ? 8 : 0);
        const int bOff = (l & 8) ? 16 : 0;    // bytes

        auto load_stage = [&](int chunk, int buf) {
            const int kc = chunk * BKB;
            const uint32_t dA = sb + buf * STT;
            const uint32_t dB = dA + STA;
            #pragma unroll
            for (int i = 0; i < 4; i++) {     // A: 128 rows
                int rr = r + 32 * i;
                CP16(dA + rr * LDSPB + u * 16,
                     (const void*)(A + (size_t)(bm + rr) * KPAD + kc + u * 16));
            }
            #pragma unroll
            for (int i = 0; i < 2; i++) {     // B: 64 rows
                int rr = r + 32 * i;
                CP16(dB + rr * LDSPB + u * 16,
                     (const void*)(Bm + (size_t)(bn + rr) * KPAD + kc + u * 16));
            }
        };

        #pragma unroll
        for (int s = 0; s < STAGES - 1; ++s) { load_stage(s, s); CP_COMMIT(); }

        for (int c = 0; c < NCH; ++c) {
            CP_WAIT1();
            __syncthreads();

            const int nc_ = c + STAGES - 1;
            if (nc_ < NCH) load_stage(nc_, nc_ % STAGES);
            CP_COMMIT();

            const int buf = c % STAGES;
            const uint32_t baseA = sb + buf * STT;
            const uint32_t baseB = baseA + STA;

            #pragma unroll
            for (int s = 0; s < 2; ++s) {
                uint32_t af[2][4];
                #pragma unroll
                for (int mi = 0; mi < 2; mi++)
                    ldmx4(af[mi], baseA + (aRow + mi * 16) * LDSPB + s * 32 + aOff);
                uint32_t bf[4][4];
                #pragma unroll
                for (int g = 0; g < 4; g++)
                    ldmx4(bf[g], baseB + (bRow + g * 16) * LDSPB + s * 32 + bOff);
                #pragma unroll
                for (int mi = 0; mi < 2; mi++)
                    #pragma unroll
                    for (int g = 0; g < 4; g++) {
                        mma_fp8(acc[mi][2 * g],     af[mi], bf[g][0], bf[g][1]);
                        mma_fp8(acc[mi][2 * g + 1], af[mi], bf[g][2], bf[g][3]);
                    }
            }
        }
    }

    // ---- epilogue ----
    // rows: bm + wid*32 + mi*16 + (l>>2) + h*8 ; cols: bn + ni*8 + (l&3)*2
    if (mode == 1) {
        #pragma unroll
        for (int mi = 0; mi < 2; mi++) {
            #pragma unroll
            for (int h = 0; h < 2; h++) {
                const int row = bm + wid * 32 + mi * 16 + (l >> 2) + h * 8;
                float rs = 0.0f;
                #pragma unroll
                for (int ni = 0; ni < 8; ni++) {
                    const int col = bn + ni * 8 + (l & 3) * 2;
                    float e0 = 0.0f, e1 = 0.0f;
                    if (col < C_CLS)
                        e0 = __expf((g_m1[col] + acc[mi][ni][h * 2 + 0] * DEQ) * NORMF);
                    if (col + 1 < C_CLS)
                        e1 = __expf((g_m1[col + 1] + acc[mi][ni][h * 2 + 1] * DEQ) * NORMF);
                    *(uint16_t*)&g_Ef8[(size_t)row * KPAD + col] =
                        f2_fp8x2(e0 * SA, e1 * SA);
                    rs += e0 + e1;
                }
                rs += __shfl_xor_sync(0xFFFFFFFFu, rs, 1);
                rs += __shfl_xor_sync(0xFFFFFFFFu, rs, 2);
                if ((l & 3) == 0) atomicAdd(&g_rowsum[row], rs);
            }
        }
    } else {
        #pragma unroll
        for (int mi = 0; mi < 2; mi++) {
            #pragma unroll
            for (int h = 0; h < 2; h++) {
                const int row = bm + wid * 32 + mi * 16 + (l >> 2) + h * 8;
                const float inv = 1.0f / g_rowsum[row];
                const float* pvrow = p_vlm + (size_t)row * C_CLS;
                float*       orow  = out   + (size_t)row * C_CLS;
                #pragma unroll
                for (int ni = 0; ni < 8; ni++) {
                    const int col = bn + ni * 8 + (l & 3) * 2;
                    #pragma unroll
                    for (int e = 0; e < 2; e++) {
                        int n = col + e;
                        if (n < C_CLS) {
                            float pt  = g_m2[n] * INV_C
                                      + acc[mi][ni][h * 2 + e] * DEQ * inv;
                            float pv  = __ldg(pvrow + n);
                            float eut = __expf(pt * __logf(pt + EPSU));
                            float euv = __expf(pv * __logf(pv + EPSU));
                            orow[n] = (eut * pt + euv * pv) / (eut + euv);
                        }
                    }
                }
            }
        }
    }
}

// ---------------------------------------------------------------------------
extern "C" void kernel_launch(void* const* d_in, const int* in_sizes, int n_in,
                              void* d_out, int out_size) {
    const float* p_tar = (const float*)d_in[0];
    const float* p_vlm = (const float*)d_in[1];
    const float* alpha = (const float*)d_in[2];
    const float* bank  = (const float*)d_in[3];
    float* out      = (float*)d_out;                       // p_mix [B,C]
    float* out_bank = out + (size_t)B_ROWS * C_CLS;        // bank_new [C,C]

    static int attr_set = 0;
    if (!attr_set) {
        cudaFuncSetAttribute(gemm_fp8, cudaFuncAttributeMaxDynamicSharedMemorySize,
                             SMEMT);
        attr_set = 1;
    }

    dim3 gg(KPAD / BN, B_ROWS / BM);  // (16, 256)

    zero_kernel<<<(C_CLS * C_CLS + 255) / 256, 256>>>();          // 1
    convB1_kernel<<<KPAD, 128>>>(bank);                           // 2
    prep_kernel<<<B_ROWS, 256>>>(p_tar, p_vlm);                   // 3
    gemm_fp8<<<gg, 128, SMEMT>>>(nullptr, nullptr, 1);            // 4 <- ncu capture
    transT_kernel<<<dim3(32, 32), 256>>>(bank);                   // 5
    convB2_kernel<<<KPAD, 128>>>();                               // 6
    gemm_fp8<<<gg, 128, SMEMT>>>(p_vlm, out, 2);                  // 7
    bank_kernel<<<(C_CLS * C_CLS + 255) / 256, 256>>>(bank, alpha, out_bank); // 8
}

// round 12
// speedup vs baseline: 3.5720x; 1.4495x over previous
#include <cuda_runtime.h>
#include <cuda_bf16.h>
#include <cuda_fp8.h>
#include <cstdint>
#include <math.h>

#define B_ROWS 32768
#define C_CLS  1000
#define KPAD   1024
#define EPSU   1e-6f
#define NORMF  0.031622776601683794f   // 1/sqrt(1000)
#define INV_C  0.001f
#define SA     128.0f                  // fp8 scale for A / E
#define SB     256.0f                  // fp8 scale for centered B residuals
#define DEQ    (1.0f / (128.0f * 256.0f))

// ---------------- scratch (__device__ globals; no allocations) --------------
__device__ uint8_t g_Af8[(size_t)B_ROWS * KPAD];   // p_tar  fp8 x128, padded
__device__ uint8_t g_Ef8[(size_t)B_ROWS * KPAD];   // E      fp8 x128, padded
__device__ uint8_t g_B1f8[(size_t)KPAD * KPAD];    // (bank - m1) x256  [n][k]
__device__ uint8_t g_B2f8[(size_t)KPAD * KPAD];    // (bank^T - m2) x256 [j][k]
__device__ float   g_BT[(size_t)KPAD * KPAD];      // bank^T fp32 staging
__device__ float   g_m1[KPAD];                     // row means of bank
__device__ float   g_m2[KPAD];                     // raw col sums of bank
__device__ float   g_rowsum[B_ROWS];
__device__ float   g_sums[(size_t)C_CLS * C_CLS];
__device__ float   g_count[C_CLS];
__device__ int     g_nzB1;                         // residual B1 has nonzero?
__device__ int     g_nzB2;                         // residual B2 has nonzero?

// ---------------- helpers ----------------------------------------------------
__device__ __forceinline__ uint16_t f2_fp8x2(float lo, float hi) {
    __nv_fp8x2_storage_t r =
        __nv_cvt_float2_to_fp8x2(make_float2(lo, hi), __NV_SATFINITE, __NV_E4M3);
    return (uint16_t)r;
}
__device__ __forceinline__ uint32_t smem_u32(const void* p) {
    uint32_t a;
    asm("{ .reg .u64 t; cvta.to.shared.u64 t, %1; cvt.u32.u64 %0, t; }"
        : "=r"(a) : "l"(p));
    return a;
}
__device__ __forceinline__ void ldmx4(uint32_t* r, uint32_t addr) {
    asm volatile("ldmatrix.sync.aligned.m8n8.x4.shared.b16 {%0,%1,%2,%3}, [%4];"
                 : "=r"(r[0]), "=r"(r[1]), "=r"(r[2]), "=r"(r[3]) : "r"(addr));
}
__device__ __forceinline__ void mma_fp8(float* c, const uint32_t* a,
                                        uint32_t b0, uint32_t b1) {
    asm volatile("mma.sync.aligned.m16n8k32.row.col.f32.e4m3.e4m3.f32 "
                 "{%0,%1,%2,%3}, {%4,%5,%6,%7}, {%8,%9}, {%0,%1,%2,%3};"
                 : "+f"(c[0]), "+f"(c[1]), "+f"(c[2]), "+f"(c[3])
                 : "r"(a[0]), "r"(a[1]), "r"(a[2]), "r"(a[3]), "r"(b0), "r"(b1));
}
#define CP16(dst, src) \
    asm volatile("cp.async.cg.shared.global [%0], [%1], 16;" :: "r"(dst), "l"(src))
#define CP_COMMIT() asm volatile("cp.async.commit_group;")
#define CP_WAIT1()  asm volatile("cp.async.wait_group 1;")

// ---------------------------------------------------------------------------
__global__ void zero_kernel() {
    int i = blockIdx.x * blockDim.x + threadIdx.x;
    if (i < C_CLS * C_CLS) g_sums[i] = 0.0f;
    if (i < B_ROWS)        g_rowsum[i] = 0.0f;
    if (i < C_CLS)         g_count[i] = 0.0f;
    if (i < KPAD)          g_m2[i] = 0.0f;
    if (i == 0) { g_nzB1 = 0; g_nzB2 = 0; }
}

// B1: row means + centered fp8 residual rows of bank [n][k] + nonzero flag
__global__ void __launch_bounds__(128) convB1_kernel(const float* __restrict__ bank) {
    const int n = blockIdx.x;     // 0..1023
    const int t = threadIdx.x;
    uint32_t* dst = reinterpret_cast<uint32_t*>(g_B1f8 + (size_t)n * KPAD);
    if (n >= C_CLS) {
        for (int u = t; u < KPAD / 4; u += 128) dst[u] = 0u;
        if (t == 0) g_m1[n] = 0.0f;
        return;
    }
    const float* row = bank + (size_t)n * C_CLS;
    float s = 0.0f;
    for (int k = t; k < C_CLS; k += 128) s += row[k];
    #pragma unroll
    for (int o = 16; o > 0; o >>= 1) s += __shfl_xor_sync(0xFFFFFFFFu, s, o);
    __shared__ float sw[4];
    if ((t & 31) == 0) sw[t >> 5] = s;
    __syncthreads();
    const float m = (sw[0] + sw[1] + sw[2] + sw[3]) * INV_C;
    if (t == 0) g_m1[n] = m;
    uint32_t nz = 0u;
    for (int u = t; u < KPAD / 4; u += 128) {
        int k = 4 * u;
        float4 v = make_float4(0.f, 0.f, 0.f, 0.f);
        if (k + 3 < C_CLS) v = *(const float4*)(row + k);  // C_CLS % 4 == 0
        uint16_t lo = f2_fp8x2((k < C_CLS) ? (v.x - m) * SB : 0.f,
                               (k < C_CLS) ? (v.y - m) * SB : 0.f);
        uint16_t hi = f2_fp8x2((k < C_CLS) ? (v.z - m) * SB : 0.f,
                               (k < C_CLS) ? (v.w - m) * SB : 0.f);
        uint32_t packed = (uint32_t)lo | ((uint32_t)hi << 16);
        dst[u] = packed;
        nz |= (packed & 0x7F7F7F7Fu);   // value-zero test (ignore sign of -0)
    }
    if (nz) atomicOr(&g_nzB1, 1);
}

// T1: tiled transpose bank -> g_BT (fp32) + column-sum atomics into g_m2
__global__ void __launch_bounds__(256) transT_kernel(const float* __restrict__ bank) {
    __shared__ float tile[32][33];
    const int tk = blockIdx.y * 32;
    const int tj = blockIdx.x * 32;
    const int jx = threadIdx.x & 31;
    const int ky = threadIdx.x >> 5;
    #pragma unroll
    for (int s = 0; s < 4; s++) {
        int k = tk + ky + s * 8, j = tj + jx;
        tile[ky + s * 8][jx] = (k < C_CLS && j < C_CLS)
                             ? bank[(size_t)k * C_CLS + j] : 0.0f;
    }
    __syncthreads();
    #pragma unroll
    for (int s = 0; s < 4; s++) {
        int j = tj + ky + s * 8, k = tk + jx;
        g_BT[(size_t)j * KPAD + k] = tile[jx][ky + s * 8];
    }
    float ps = 0.0f;
    #pragma unroll
    for (int s = 0; s < 4; s++) ps += tile[ky + s * 8][jx];
    __syncthreads();
    tile[ky][jx] = ps;
    __syncthreads();
    if (ky == 0) {
        float tot = 0.0f;
        #pragma unroll
        for (int y = 0; y < 8; y++) tot += tile[y][jx];
        if (tj + jx < C_CLS) atomicAdd(&g_m2[tj + jx], tot);
    }
}

// T2: centered fp8 residual rows of bank^T [j][k] + nonzero flag
__global__ void __launch_bounds__(128) convB2_kernel() {
    const int j = blockIdx.x;
    const int t = threadIdx.x;
    uint32_t* dst = reinterpret_cast<uint32_t*>(g_B2f8 + (size_t)j * KPAD);
    if (j >= C_CLS) {
        for (int u = t; u < KPAD / 4; u += 128) dst[u] = 0u;
        return;
    }
    const float m = g_m2[j] * INV_C;
    const float* row = g_BT + (size_t)j * KPAD;
    uint32_t nz = 0u;
    for (int u = t; u < KPAD / 4; u += 128) {
        int k = 4 * u;
        if (k + 3 < C_CLS) {
            float4 v = *(const float4*)(row + k);
            uint16_t lo = f2_fp8x2((v.x - m) * SB, (v.y - m) * SB);
            uint16_t hi = f2_fp8x2((v.z - m) * SB, (v.w - m) * SB);
            uint32_t packed = (uint32_t)lo | ((uint32_t)hi << 16);
            dst[u] = packed;
            nz |= (packed & 0x7F7F7F7Fu);
        } else {
            dst[u] = 0u;
        }
    }
    if (nz) atomicOr(&g_nzB2, 1);
}

// prep: p_tar -> fp8 (g_Af8, only if gemm1's mainloop will run) + dual argmax
// + agreement + fused scatter-add
__global__ void __launch_bounds__(256) prep_kernel(const float* __restrict__ p_tar,
                                                   const float* __restrict__ p_vlm) {
    const int row = blockIdx.x;
    const int t   = threadIdx.x;
    const float4* pt4 = reinterpret_cast<const float4*>(p_tar + (size_t)row * C_CLS);
    const float4* pv4 = reinterpret_cast<const float4*>(p_vlm + (size_t)row * C_CLS);
    uint32_t* arow = reinterpret_cast<uint32_t*>(g_Af8 + (size_t)row * KPAD);
    const bool needA = (g_nzB1 != 0) && (g_nzB2 != 0);  // A only read by gemm1 mainloop

    float vt = -1.0f, vv = -1.0f;
    int   it = 0,     iv = 0;
    float4 a = make_float4(0.f, 0.f, 0.f, 0.f);
    const int k = 4 * t;
    const bool act = (t < KPAD / 4) && (k < C_CLS);
    if (act) {
        a = pt4[t];
        float4 b = pv4[t];
        if (a.x > vt) { vt = a.x; it = k; }
        if (a.y > vt) { vt = a.y; it = k + 1; }
        if (a.z > vt) { vt = a.z; it = k + 2; }
        if (a.w > vt) { vt = a.w; it = k + 3; }
        if (b.x > vv) { vv = b.x; iv = k; }
        if (b.y > vv) { vv = b.y; iv = k + 1; }
        if (b.z > vv) { vv = b.z; iv = k + 2; }
        if (b.w > vv) { vv = b.w; iv = k + 3; }
        if (needA) {
            uint16_t lo = f2_fp8x2(a.x * SA, a.y * SA);
            uint16_t hi = f2_fp8x2(a.z * SA, a.w * SA);
            arow[t] = (uint32_t)lo | ((uint32_t)hi << 16);
        }
    } else if (t < KPAD / 4 && needA) {
        arow[t] = 0u;
    }
    const int lane = t & 31;
    #pragma unroll
    for (int off = 16; off > 0; off >>= 1) {
        float ov = __shfl_down_sync(0xFFFFFFFFu, vt, off);
        int   oi = __shfl_down_sync(0xFFFFFFFFu, it, off);
        if (ov > vt || (ov == vt && oi < it)) { vt = ov; it = oi; }
        ov = __shfl_down_sync(0xFFFFFFFFu, vv, off);
        oi = __shfl_down_sync(0xFFFFFFFFu, iv, off);
        if (ov > vv || (ov == vv && oi < iv)) { vv = ov; iv = oi; }
    }
    __shared__ float swt[8], swv[8];
    __shared__ int   sit[8], siv[8];
    __shared__ int   s_lab;
    if (lane == 0) { swt[t >> 5] = vt; sit[t >> 5] = it; swv[t >> 5] = vv; siv[t >> 5] = iv; }
    __syncthreads();
    if (t == 0) {
        float bt = swt[0], bv = swv[0];
        int   bi = sit[0], bj = siv[0];
        #pragma unroll
        for (int w = 1; w < 8; w++) {
            if (swt[w] > bt || (swt[w] == bt && sit[w] < bi)) { bt = swt[w]; bi = sit[w]; }
            if (swv[w] > bv || (swv[w] == bv && siv[w] < bj)) { bv = swv[w]; bj = siv[w]; }
        }
        if (bi == bj) { s_lab = bi; atomicAdd(&g_count[bi], 1.0f); }
        else          { s_lab = -1; }
    }
    __syncthreads();
    const int c = s_lab;
    if (c >= 0 && act) {   // fused scatter (rare: ~B/C rows agree)
        float* dst = g_sums + (size_t)c * C_CLS + k;
        atomicAdd(dst + 0, a.x);
        if (k + 1 < C_CLS) atomicAdd(dst + 1, a.y);
        if (k + 2 < C_CLS) atomicAdd(dst + 2, a.z);
        if (k + 3 < C_CLS) atomicAdd(dst + 3, a.w);
    }
}

__global__ void bank_kernel(const float* __restrict__ bank,
                            const float* __restrict__ alpha,
                            float* __restrict__ out_bank) {
    int i = blockIdx.x * blockDim.x + threadIdx.x;
    if (i >= C_CLS * C_CLS) return;
    int   c   = i / C_CLS;
    float a   = alpha[0];
    float cnt = g_count[c];
    float b   = bank[i];
    out_bank[i] = (cnt > 0.0f) ? (a * b + (1.0f - a) * (g_sums[i] / cnt)) : b;
}

// ---------------------------------------------------------------------------
// fp8 HMMA GEMM (NT): D[bm:+128, bn:+64] = A * B^T (residual part)
// 128 thr, 4 warps, warp tile 32x64, cp.async 3-stage, 4 CTAs/SM.
// FAST PATHS (exact):
//  - mode 1 && nzB2==0  -> E/rowsum never consumed -> immediate exit.
//  - nzB==0             -> mainloop skipped, acc stays +0 (bit-identical).
//  - mode 2 && nzB2==0  -> coalesced float4 stream, per-col pt/eut from smem.
#define BM     128
#define BN     64
#define BKB    64                    // k bytes per chunk
#define STAGES 3
#define LDSPB  80                    // padded smem row stride (bytes)
#define NCH    (KPAD / BKB)          // 16
#define STA    (BM * LDSPB)          // 10240
#define STB    (BN * LDSPB)          // 5120
#define STT    (STA + STB)           // 15360
#define SMEMT  (STAGES * STT)        // 46080

__global__ void __launch_bounds__(128, 4)
gemm_fp8(const float* __restrict__ p_vlm,
         float* __restrict__ out,
         int mode) {
    extern __shared__ char smem[];
    const uint32_t sb = smem_u32(smem);

    const int nzB2 = g_nzB2;
    if (mode == 1 && nzB2 == 0) return;   // E & rowsum would be dead values

    const uint8_t* __restrict__ A  = (mode == 1) ? g_Af8  : g_Ef8;
    const uint8_t* __restrict__ Bm = (mode == 1) ? g_B1f8 : g_B2f8;
    const int nzB = (mode == 1) ? g_nzB1 : nzB2;

    const int t   = threadIdx.x;
    const int wid = t >> 5;              // 0..3 -> m offset wid*32
    const int l   = t & 31;
    const int bm  = blockIdx.y * BM;
    const int bn  = blockIdx.x * BN;

    // ---- mode-2 fast path: pure elementwise stream, coalesced float4 ----
    if (mode == 2 && nzB2 == 0) {
        __shared__ float spt[BN], seut[BN];
        if (t < BN) {
            int coln = bn + t;
            float ptc = (coln < C_CLS) ? g_m2[coln] * INV_C : 0.0f;
            spt[t]  = ptc;
            seut[t] = __expf(ptc * __logf(ptc + EPSU));
        }
        __syncthreads();
        // tile = rows [bm, bm+128) x cols [bn, bn+64) ; 16 float4 per row
        #pragma unroll
        for (int i = 0; i < 16; i++) {
            int idx = t + 128 * i;            // 0..2047
            int rr  = idx >> 4;               // 0..127
            int c4  = idx & 15;               // 0..15
            int col = bn + c4 * 4;
            if (col + 3 >= C_CLS) continue;   // C_CLS % 4 == 0
            const size_t base = (size_t)(bm + rr) * C_CLS + col;
            float4 pv = *(const float4*)(p_vlm + base);
            float4 o;
            {
                float pt = spt[c4 * 4 + 0], eut = seut[c4 * 4 + 0];
                float euv = __expf(pv.x * __logf(pv.x + EPSU));
                o.x = (eut * pt + euv * pv.x) / (eut + euv);
            }
            {
                float pt = spt[c4 * 4 + 1], eut = seut[c4 * 4 + 1];
                float euv = __expf(pv.y * __logf(pv.y + EPSU));
                o.y = (eut * pt + euv * pv.y) / (eut + euv);
            }
            {
                float pt = spt[c4 * 4 + 2], eut = seut[c4 * 4 + 2];
                float euv = __expf(pv.z * __logf(pv.z + EPSU));
                o.z = (eut * pt + euv * pv.z) / (eut + euv);
            }
            {
                float pt = spt[c4 * 4 + 3], eut = seut[c4 * 4 + 3];
                float euv = __expf(pv.w * __logf(pv.w + EPSU));
                o.w = (eut * pt + euv * pv.w) / (eut + euv);
            }
            *(float4*)(out + base) = o;
        }
        return;
    }

    const int r = t >> 2, u = t & 3;     // loader: 32 rows x 4x16B per pass

    float acc[2][8][4];
    #pragma unroll
    for (int mi = 0; mi < 2; mi++)
        #pragma unroll
        for (int ni = 0; ni < 8; ni++)
            #pragma unroll
            for (int kk = 0; kk < 4; kk++) acc[mi][ni][kk] = 0.0f;

    if (nzB) {   // residual GEMM only when B residual is not value-zero
        const int aRow = wid * 32 + (l & 15);
        const int aOff = (l & 16) ? 16 : 0;   // bytes
        const int bRow = (l & 7) + ((l & 16) ? 8 : 0);
        const int bOff = (l & 8) ? 16 : 0;    // bytes

        auto load_stage = [&](int chunk, int buf) {
            const int kc = chunk * BKB;
            const uint32_t dA = sb + buf * STT;
            const uint32_t dB = dA + STA;
            #pragma unroll
            for (int i = 0; i < 4; i++) {     // A: 128 rows
                int rr = r + 32 * i;
                CP16(dA + rr * LDSPB + u * 16,
                     (const void*)(A + (size_t)(bm + rr) * KPAD + kc + u * 16));
            }
            #pragma unroll
            for (int i = 0; i < 2; i++) {     // B: 64 rows
                int rr = r + 32 * i;
                CP16(dB + rr * LDSPB + u * 16,
                     (const void*)(Bm + (size_t)(bn + rr) * KPAD + kc + u * 16));
            }
        };

        #pragma unroll
        for (int s = 0; s < STAGES - 1; ++s) { load_stage(s, s); CP_COMMIT(); }

        for (int c = 0; c < NCH; ++c) {
            CP_WAIT1();
            __syncthreads();

            const int nc_ = c + STAGES - 1;
            if (nc_ < NCH) load_stage(nc_, nc_ % STAGES);
            CP_COMMIT();

            const int buf = c % STAGES;
            const uint32_t baseA = sb + buf * STT;
            const uint32_t baseB = baseA + STA;

            #pragma unroll
            for (int s = 0; s < 2; ++s) {
                uint32_t af[2][4];
                #pragma unroll
                for (int mi = 0; mi < 2; mi++)
                    ldmx4(af[mi], baseA + (aRow + mi * 16) * LDSPB + s * 32 + aOff);
                uint32_t bf[4][4];
                #pragma unroll
                for (int g = 0; g < 4; g++)
                    ldmx4(bf[g], baseB + (bRow + g * 16) * LDSPB + s * 32 + bOff);
                #pragma unroll
                for (int mi = 0; mi < 2; mi++)
                    #pragma unroll
                    for (int g = 0; g < 4; g++) {
                        mma_fp8(acc[mi][2 * g],     af[mi], bf[g][0], bf[g][1]);
                        mma_fp8(acc[mi][2 * g + 1], af[mi], bf[g][2], bf[g][3]);
                    }
            }
        }
    }

    // ---- epilogue (general path) ----
    // rows: bm + wid*32 + mi*16 + (l>>2) + h*8 ; cols: bn + ni*8 + (l&3)*2
    if (mode == 1) {
        #pragma unroll
        for (int mi = 0; mi < 2; mi++) {
            #pragma unroll
            for (int h = 0; h < 2; h++) {
                const int row = bm + wid * 32 + mi * 16 + (l >> 2) + h * 8;
                float rs = 0.0f;
                #pragma unroll
                for (int ni = 0; ni < 8; ni++) {
                    const int col = bn + ni * 8 + (l & 3) * 2;
                    float e0 = 0.0f, e1 = 0.0f;
                    if (col < C_CLS)
                        e0 = __expf((g_m1[col] + acc[mi][ni][h * 2 + 0] * DEQ) * NORMF);
                    if (col + 1 < C_CLS)
                        e1 = __expf((g_m1[col + 1] + acc[mi][ni][h * 2 + 1] * DEQ) * NORMF);
                    *(uint16_t*)&g_Ef8[(size_t)row * KPAD + col] =
                        f2_fp8x2(e0 * SA, e1 * SA);
                    rs += e0 + e1;
                }
                rs += __shfl_xor_sync(0xFFFFFFFFu, rs, 1);
                rs += __shfl_xor_sync(0xFFFFFFFFu, rs, 2);
                if ((l & 3) == 0) atomicAdd(&g_rowsum[row], rs);
            }
        }
    } else {
        #pragma unroll
        for (int mi = 0; mi < 2; mi++) {
            #pragma unroll
            for (int h = 0; h < 2; h++) {
                const int row = bm + wid * 32 + mi * 16 + (l >> 2) + h * 8;
                const float inv = 1.0f / g_rowsum[row];
                const float* pvrow = p_vlm + (size_t)row * C_CLS;
                float*       orow  = out   + (size_t)row * C_CLS;
                #pragma unroll
                for (int ni = 0; ni < 8; ni++) {
                    const int col = bn + ni * 8 + (l & 3) * 2;
                    #pragma unroll
                    for (int e = 0; e < 2; e++) {
                        int n = col + e;
                        if (n < C_CLS) {
                            float pt  = g_m2[n] * INV_C
                                      + acc[mi][ni][h * 2 + e] * DEQ * inv;
                            float pv  = __ldg(pvrow + n);
                            float eut = __expf(pt * __logf(pt + EPSU));
                            float euv = __expf(pv * __logf(pv + EPSU));
                            orow[n] = (eut * pt + euv * pv) / (eut + euv);
                        }
                    }
                }
            }
        }
    }
}

// ---------------------------------------------------------------------------
extern "C" void kernel_launch(void* const* d_in, const int* in_sizes, int n_in,
                              void* d_out, int out_size) {
    const float* p_tar = (const float*)d_in[0];
    const float* p_vlm = (const float*)d_in[1];
    const float* alpha = (const float*)d_in[2];
    const float* bank  = (const float*)d_in[3];
    float* out      = (float*)d_out;                       // p_mix [B,C]
    float* out_bank = out + (size_t)B_ROWS * C_CLS;        // bank_new [C,C]

    static int attr_set = 0;
    if (!attr_set) {
        cudaFuncSetAttribute(gemm_fp8, cudaFuncAttributeMaxDynamicSharedMemorySize,
                             SMEMT);
        attr_set = 1;
    }

    dim3 gg(KPAD / BN, B_ROWS / BM);  // (16, 256)

    zero_kernel<<<(C_CLS * C_CLS + 255) / 256, 256>>>();          // 1
    convB1_kernel<<<KPAD, 128>>>(bank);                           // 2
    transT_kernel<<<dim3(32, 32), 256>>>(bank);                   // 3
    convB2_kernel<<<KPAD, 128>>>();                               // 4
    prep_kernel<<<B_ROWS, 256>>>(p_tar, p_vlm);                   // 5
    gemm_fp8<<<gg, 128, SMEMT>>>(nullptr, nullptr, 1);            // 6
    gemm_fp8<<<gg, 128, SMEMT>>>(p_vlm, out, 2);                  // 7
    bank_kernel<<<(C_CLS * C_CLS + 255) / 256, 256>>>(bank, alpha, out_bank); // 8
}

// round 13
// speedup vs baseline: 6.3307x; 1.7723x over previous
#include <cuda_runtime.h>
#include <cuda_bf16.h>
#include <cuda_fp8.h>
#include <cstdint>
#include <math.h>

#define B_ROWS 32768
#define C_CLS  1000
#define KPAD   1024
#define EPSU   1e-6f
#define NORMF  0.031622776601683794f   // 1/sqrt(1000)
#define INV_C  0.001f
#define SA     128.0f                  // fp8 scale for A / E
#define SB     256.0f                  // fp8 scale for centered B residuals
#define DEQ    (1.0f / (128.0f * 256.0f))

// ---------------- scratch (__device__ globals; no allocations) --------------
__device__ uint8_t g_Af8[(size_t)B_ROWS * KPAD];   // p_tar  fp8 x128, padded
__device__ uint8_t g_Ef8[(size_t)B_ROWS * KPAD];   // E      fp8 x128, padded
__device__ uint8_t g_B1f8[(size_t)KPAD * KPAD];    // (bank - m1) x256  [n][k]
__device__ uint8_t g_B2f8[(size_t)KPAD * KPAD];    // (bank^T - m2) x256 [j][k]
__device__ float   g_BT[(size_t)KPAD * KPAD];      // bank^T fp32 staging
__device__ float   g_m1[KPAD];                     // row means of bank
__device__ float   g_m2[KPAD];                     // raw col sums of bank
__device__ float   g_ptc[KPAD];                    // fast-path pt per column
__device__ float   g_eutc[KPAD];                   // fast-path eut per column
__device__ float   g_rowsum[B_ROWS];
__device__ float   g_sums[(size_t)C_CLS * C_CLS];
__device__ float   g_count[C_CLS];
__device__ int     g_nzB1;                         // residual B1 has nonzero?
__device__ int     g_nzB2;                         // residual B2 has nonzero?

// ---------------- helpers ----------------------------------------------------
__device__ __forceinline__ uint16_t f2_fp8x2(float lo, float hi) {
    __nv_fp8x2_storage_t r =
        __nv_cvt_float2_to_fp8x2(make_float2(lo, hi), __NV_SATFINITE, __NV_E4M3);
    return (uint16_t)r;
}
__device__ __forceinline__ uint32_t smem_u32(const void* p) {
    uint32_t a;
    asm("{ .reg .u64 t; cvta.to.shared.u64 t, %1; cvt.u32.u64 %0, t; }"
        : "=r"(a) : "l"(p));
    return a;
}
__device__ __forceinline__ void ldmx4(uint32_t* r, uint32_t addr) {
    asm volatile("ldmatrix.sync.aligned.m8n8.x4.shared.b16 {%0,%1,%2,%3}, [%4];"
                 : "=r"(r[0]), "=r"(r[1]), "=r"(r[2]), "=r"(r[3]) : "r"(addr));
}
__device__ __forceinline__ void mma_fp8(float* c, const uint32_t* a,
                                        uint32_t b0, uint32_t b1) {
    asm volatile("mma.sync.aligned.m16n8k32.row.col.f32.e4m3.e4m3.f32 "
                 "{%0,%1,%2,%3}, {%4,%5,%6,%7}, {%8,%9}, {%0,%1,%2,%3};"
                 : "+f"(c[0]), "+f"(c[1]), "+f"(c[2]), "+f"(c[3])
                 : "r"(a[0]), "r"(a[1]), "r"(a[2]), "r"(a[3]), "r"(b0), "r"(b1));
}
#define CP16(dst, src) \
    asm volatile("cp.async.cg.shared.global [%0], [%1], 16;" :: "r"(dst), "l"(src))
#define CP_COMMIT() asm volatile("cp.async.commit_group;")
#define CP_WAIT1()  asm volatile("cp.async.wait_group 1;")

// ---------------------------------------------------------------------------
__global__ void zero_kernel() {
    int i = blockIdx.x * blockDim.x + threadIdx.x;
    if (i < C_CLS * C_CLS) g_sums[i] = 0.0f;
    if (i < B_ROWS)        g_rowsum[i] = 0.0f;
    if (i < C_CLS)         g_count[i] = 0.0f;
    if (i < KPAD)          g_m2[i] = 0.0f;
    if (i == 0) { g_nzB1 = 0; g_nzB2 = 0; }
}

// B1: row means + centered fp8 residual rows of bank [n][k] + nonzero flag
__global__ void __launch_bounds__(128) convB1_kernel(const float* __restrict__ bank) {
    const int n = blockIdx.x;     // 0..1023
    const int t = threadIdx.x;
    uint32_t* dst = reinterpret_cast<uint32_t*>(g_B1f8 + (size_t)n * KPAD);
    if (n >= C_CLS) {
        for (int u = t; u < KPAD / 4; u += 128) dst[u] = 0u;
        if (t == 0) g_m1[n] = 0.0f;
        return;
    }
    const float* row = bank + (size_t)n * C_CLS;
    float s = 0.0f;
    for (int k = t; k < C_CLS; k += 128) s += row[k];
    #pragma unroll
    for (int o = 16; o > 0; o >>= 1) s += __shfl_xor_sync(0xFFFFFFFFu, s, o);
    __shared__ float sw[4];
    if ((t & 31) == 0) sw[t >> 5] = s;
    __syncthreads();
    const float m = (sw[0] + sw[1] + sw[2] + sw[3]) * INV_C;
    if (t == 0) g_m1[n] = m;
    uint32_t nz = 0u;
    for (int u = t; u < KPAD / 4; u += 128) {
        int k = 4 * u;
        float4 v = make_float4(0.f, 0.f, 0.f, 0.f);
        if (k + 3 < C_CLS) v = *(const float4*)(row + k);  // C_CLS % 4 == 0
        uint16_t lo = f2_fp8x2((k < C_CLS) ? (v.x - m) * SB : 0.f,
                               (k < C_CLS) ? (v.y - m) * SB : 0.f);
        uint16_t hi = f2_fp8x2((k < C_CLS) ? (v.z - m) * SB : 0.f,
                               (k < C_CLS) ? (v.w - m) * SB : 0.f);
        uint32_t packed = (uint32_t)lo | ((uint32_t)hi << 16);
        dst[u] = packed;
        nz |= (packed & 0x7F7F7F7Fu);   // value-zero test (ignore sign of -0)
    }
    if (nz) atomicOr(&g_nzB1, 1);
}

// T1: tiled transpose bank -> g_BT (fp32) + column-sum atomics into g_m2
__global__ void __launch_bounds__(256) transT_kernel(const float* __restrict__ bank) {
    __shared__ float tile[32][33];
    const int tk = blockIdx.y * 32;
    const int tj = blockIdx.x * 32;
    const int jx = threadIdx.x & 31;
    const int ky = threadIdx.x >> 5;
    #pragma unroll
    for (int s = 0; s < 4; s++) {
        int k = tk + ky + s * 8, j = tj + jx;
        tile[ky + s * 8][jx] = (k < C_CLS && j < C_CLS)
                             ? bank[(size_t)k * C_CLS + j] : 0.0f;
    }
    __syncthreads();
    #pragma unroll
    for (int s = 0; s < 4; s++) {
        int j = tj + ky + s * 8, k = tk + jx;
        g_BT[(size_t)j * KPAD + k] = tile[jx][ky + s * 8];
    }
    float ps = 0.0f;
    #pragma unroll
    for (int s = 0; s < 4; s++) ps += tile[ky + s * 8][jx];
    __syncthreads();
    tile[ky][jx] = ps;
    __syncthreads();
    if (ky == 0) {
        float tot = 0.0f;
        #pragma unroll
        for (int y = 0; y < 8; y++) tot += tile[y][jx];
        if (tj + jx < C_CLS) atomicAdd(&g_m2[tj + jx], tot);
    }
}

// T2: centered fp8 residual rows of bank^T [j][k] + nonzero flag
//     + per-column fast-path constants pt[j], eut[j]
__global__ void __launch_bounds__(128) convB2_kernel() {
    const int j = blockIdx.x;
    const int t = threadIdx.x;
    uint32_t* dst = reinterpret_cast<uint32_t*>(g_B2f8 + (size_t)j * KPAD);
    if (j >= C_CLS) {
        for (int u = t; u < KPAD / 4; u += 128) dst[u] = 0u;
        if (t == 0) { g_ptc[j] = 0.0f; g_eutc[j] = 1.0f; }
        return;
    }
    const float m = g_m2[j] * INV_C;
    if (t == 0) {
        g_ptc[j]  = m;
        g_eutc[j] = __expf(m * __logf(m + EPSU));
    }
    const float* row = g_BT + (size_t)j * KPAD;
    uint32_t nz = 0u;
    for (int u = t; u < KPAD / 4; u += 128) {
        int k = 4 * u;
        if (k + 3 < C_CLS) {
            float4 v = *(const float4*)(row + k);
            uint16_t lo = f2_fp8x2((v.x - m) * SB, (v.y - m) * SB);
            uint16_t hi = f2_fp8x2((v.z - m) * SB, (v.w - m) * SB);
            uint32_t packed = (uint32_t)lo | ((uint32_t)hi << 16);
            dst[u] = packed;
            nz |= (packed & 0x7F7F7F7Fu);
        } else {
            dst[u] = 0u;
        }
    }
    if (nz) atomicOr(&g_nzB2, 1);
}

// prep: dual argmax + agreement + fused scatter-add
//   + p_tar -> fp8 A (only if gemm1's mainloop will run)
//   + FUSED uncertainty mixing -> out when nzB2 == 0 (p_vlm read exactly once)
__global__ void __launch_bounds__(256) prep_kernel(const float* __restrict__ p_tar,
                                                   const float* __restrict__ p_vlm,
                                                   float* __restrict__ out) {
    const int row = blockIdx.x;
    const int t   = threadIdx.x;
    const float4* pt4 = reinterpret_cast<const float4*>(p_tar + (size_t)row * C_CLS);
    const float4* pv4 = reinterpret_cast<const float4*>(p_vlm + (size_t)row * C_CLS);
    uint32_t* arow = reinterpret_cast<uint32_t*>(g_Af8 + (size_t)row * KPAD);
    const int  nzB2  = g_nzB2;
    const bool needA = (g_nzB1 != 0) && (nzB2 != 0);   // A only read by gemm1 mainloop

    float vt = -1.0f, vv = -1.0f;
    int   it = 0,     iv = 0;
    float4 a = make_float4(0.f, 0.f, 0.f, 0.f);
    const int k = 4 * t;
    const bool act = (t < KPAD / 4) && (k < C_CLS);
    if (act) {
        a = pt4[t];
        float4 b = pv4[t];
        if (a.x > vt) { vt = a.x; it = k; }
        if (a.y > vt) { vt = a.y; it = k + 1; }
        if (a.z > vt) { vt = a.z; it = k + 2; }
        if (a.w > vt) { vt = a.w; it = k + 3; }
        if (b.x > vv) { vv = b.x; iv = k; }
        if (b.y > vv) { vv = b.y; iv = k + 1; }
        if (b.z > vv) { vv = b.z; iv = k + 2; }
        if (b.w > vv) { vv = b.w; iv = k + 3; }
        if (needA) {
            uint16_t lo = f2_fp8x2(a.x * SA, a.y * SA);
            uint16_t hi = f2_fp8x2(a.z * SA, a.w * SA);
            arow[t] = (uint32_t)lo | ((uint32_t)hi << 16);
        }
        if (nzB2 == 0) {   // fast-path mixing: constants per column, pv in regs
            float4 pc = *(const float4*)(g_ptc + k);
            float4 ec = *(const float4*)(g_eutc + k);
            float4 o;
            float euv;
            euv = __expf(b.x * __logf(b.x + EPSU));
            o.x = (ec.x * pc.x + euv * b.x) / (ec.x + euv);
            euv = __expf(b.y * __logf(b.y + EPSU));
            o.y = (ec.y * pc.y + euv * b.y) / (ec.y + euv);
            euv = __expf(b.z * __logf(b.z + EPSU));
            o.z = (ec.z * pc.z + euv * b.z) / (ec.z + euv);
            euv = __expf(b.w * __logf(b.w + EPSU));
            o.w = (ec.w * pc.w + euv * b.w) / (ec.w + euv);
            *(float4*)(out + (size_t)row * C_CLS + k) = o;
        }
    } else if (t < KPAD / 4 && needA) {
        arow[t] = 0u;
    }
    const int lane = t & 31;
    #pragma unroll
    for (int off = 16; off > 0; off >>= 1) {
        float ov = __shfl_down_sync(0xFFFFFFFFu, vt, off);
        int   oi = __shfl_down_sync(0xFFFFFFFFu, it, off);
        if (ov > vt || (ov == vt && oi < it)) { vt = ov; it = oi; }
        ov = __shfl_down_sync(0xFFFFFFFFu, vv, off);
        oi = __shfl_down_sync(0xFFFFFFFFu, iv, off);
        if (ov > vv || (ov == vv && oi < iv)) { vv = ov; iv = oi; }
    }
    __shared__ float swt[8], swv[8];
    __shared__ int   sit[8], siv[8];
    __shared__ int   s_lab;
    if (lane == 0) { swt[t >> 5] = vt; sit[t >> 5] = it; swv[t >> 5] = vv; siv[t >> 5] = iv; }
    __syncthreads();
    if (t == 0) {
        float bt = swt[0], bv = swv[0];
        int   bi = sit[0], bj = siv[0];
        #pragma unroll
        for (int w = 1; w < 8; w++) {
            if (swt[w] > bt || (swt[w] == bt && sit[w] < bi)) { bt = swt[w]; bi = sit[w]; }
            if (swv[w] > bv || (swv[w] == bv && siv[w] < bj)) { bv = swv[w]; bj = siv[w]; }
        }
        if (bi == bj) { s_lab = bi; atomicAdd(&g_count[bi], 1.0f); }
        else          { s_lab = -1; }
    }
    __syncthreads();
    const int c = s_lab;
    if (c >= 0 && act) {   // fused scatter (rare: ~B/C rows agree)
        float* dst = g_sums + (size_t)c * C_CLS + k;
        atomicAdd(dst + 0, a.x);
        if (k + 1 < C_CLS) atomicAdd(dst + 1, a.y);
        if (k + 2 < C_CLS) atomicAdd(dst + 2, a.z);
        if (k + 3 < C_CLS) atomicAdd(dst + 3, a.w);
    }
}

__global__ void bank_kernel(const float* __restrict__ bank,
                            const float* __restrict__ alpha,
                            float* __restrict__ out_bank) {
    int i = blockIdx.x * blockDim.x + threadIdx.x;
    if (i >= C_CLS * C_CLS) return;
    int   c   = i / C_CLS;
    float a   = alpha[0];
    float cnt = g_count[c];
    float b   = bank[i];
    out_bank[i] = (cnt > 0.0f) ? (a * b + (1.0f - a) * (g_sums[i] / cnt)) : b;
}

// ---------------------------------------------------------------------------
// fp8 HMMA GEMM (NT): D[bm:+128, bn:+64] = A * B^T (residual part)
// 128 thr, 4 warps, warp tile 32x64, cp.async 3-stage, 4 CTAs/SM.
// FAST PATHS (exact):
//  - nzB2==0            -> both modes exit (E/rowsum dead; out written by prep)
//  - nzB==0 (general)   -> mainloop skipped, acc stays +0 (bit-identical)
#define BM     128
#define BN     64
#define BKB    64                    // k bytes per chunk
#define STAGES 3
#define LDSPB  80                    // padded smem row stride (bytes)
#define NCH    (KPAD / BKB)          // 16
#define STA    (BM * LDSPB)          // 10240
#define STB    (BN * LDSPB)          // 5120
#define STT    (STA + STB)           // 15360
#define SMEMT  (STAGES * STT)        // 46080

__global__ void __launch_bounds__(128, 4)
gemm_fp8(const float* __restrict__ p_vlm,
         float* __restrict__ out,
         int mode) {
    extern __shared__ char smem[];
    const uint32_t sb = smem_u32(smem);

    const int nzB2 = g_nzB2;
    if (nzB2 == 0) return;   // fast path handled entirely by prep_kernel

    const uint8_t* __restrict__ A  = (mode == 1) ? g_Af8  : g_Ef8;
    const uint8_t* __restrict__ Bm = (mode == 1) ? g_B1f8 : g_B2f8;
    const int nzB = (mode == 1) ? g_nzB1 : nzB2;

    const int t   = threadIdx.x;
    const int wid = t >> 5;              // 0..3 -> m offset wid*32
    const int l   = t & 31;
    const int bm  = blockIdx.y * BM;
    const int bn  = blockIdx.x * BN;

    const int r = t >> 2, u = t & 3;     // loader: 32 rows x 4x16B per pass

    float acc[2][8][4];
    #pragma unroll
    for (int mi = 0; mi < 2; mi++)
        #pragma unroll
        for (int ni = 0; ni < 8; ni++)
            #pragma unroll
            for (int kk = 0; kk < 4; kk++) acc[mi][ni][kk] = 0.0f;

    if (nzB) {   // residual GEMM only when B residual is not value-zero
        const int aRow = wid * 32 + (l & 15);
        const int aOff = (l & 16) ? 16 : 0;   // bytes
        const int bRow = (l & 7) + ((l & 16) ? 8 : 0);
        const int bOff = (l & 8) ? 16 : 0;    // bytes

        auto load_stage = [&](int chunk, int buf) {
            const int kc = chunk * BKB;
            const uint32_t dA = sb + buf * STT;
            const uint32_t dB = dA + STA;
            #pragma unroll
            for (int i = 0; i < 4; i++) {     // A: 128 rows
                int rr = r + 32 * i;
                CP16(dA + rr * LDSPB + u * 16,
                     (const void*)(A + (size_t)(bm + rr) * KPAD + kc + u * 16));
            }
            #pragma unroll
            for (int i = 0; i < 2; i++) {     // B: 64 rows
                int rr = r + 32 * i;
                CP16(dB + rr * LDSPB + u * 16,
                     (const void*)(Bm + (size_t)(bn + rr) * KPAD + kc + u * 16));
            }
        };

        #pragma unroll
        for (int s = 0; s < STAGES - 1; ++s) { load_stage(s, s); CP_COMMIT(); }

        for (int c = 0; c < NCH; ++c) {
            CP_WAIT1();
            __syncthreads();

            const int nc_ = c + STAGES - 1;
            if (nc_ < NCH) load_stage(nc_, nc_ % STAGES);
            CP_COMMIT();

            const int buf = c % STAGES;
            const uint32_t baseA = sb + buf * STT;
            const uint32_t baseB = baseA + STA;

            #pragma unroll
            for (int s = 0; s < 2; ++s) {
                uint32_t af[2][4];
                #pragma unroll
                for (int mi = 0; mi < 2; mi++)
                    ldmx4(af[mi], baseA + (aRow + mi * 16) * LDSPB + s * 32 + aOff);
                uint32_t bf[4][4];
                #pragma unroll
                for (int g = 0; g < 4; g++)
                    ldmx4(bf[g], baseB + (bRow + g * 16) * LDSPB + s * 32 + bOff);
                #pragma unroll
                for (int mi = 0; mi < 2; mi++)
                    #pragma unroll
                    for (int g = 0; g < 4; g++) {
                        mma_fp8(acc[mi][2 * g],     af[mi], bf[g][0], bf[g][1]);
                        mma_fp8(acc[mi][2 * g + 1], af[mi], bf[g][2], bf[g][3]);
                    }
            }
        }
    }

    // ---- epilogue (general path) ----
    // rows: bm + wid*32 + mi*16 + (l>>2) + h*8 ; cols: bn + ni*8 + (l&3)*2
    if (mode == 1) {
        #pragma unroll
        for (int mi = 0; mi < 2; mi++) {
            #pragma unroll
            for (int h = 0; h < 2; h++) {
                const int row = bm + wid * 32 + mi * 16 + (l >> 2) + h * 8;
                float rs = 0.0f;
                #pragma unroll
                for (int ni = 0; ni < 8; ni++) {
                    const int col = bn + ni * 8 + (l & 3) * 2;
                    float e0 = 0.0f, e1 = 0.0f;
                    if (col < C_CLS)
                        e0 = __expf((g_m1[col] + acc[mi][ni][h * 2 + 0] * DEQ) * NORMF);
                    if (col + 1 < C_CLS)
                        e1 = __expf((g_m1[col + 1] + acc[mi][ni][h * 2 + 1] * DEQ) * NORMF);
                    *(uint16_t*)&g_Ef8[(size_t)row * KPAD + col] =
                        f2_fp8x2(e0 * SA, e1 * SA);
                    rs += e0 + e1;
                }
                rs += __shfl_xor_sync(0xFFFFFFFFu, rs, 1);
                rs += __shfl_xor_sync(0xFFFFFFFFu, rs, 2);
                if ((l & 3) == 0) atomicAdd(&g_rowsum[row], rs);
            }
        }
    } else {
        #pragma unroll
        for (int mi = 0; mi < 2; mi++) {
            #pragma unroll
            for (int h = 0; h < 2; h++) {
                const int row = bm + wid * 32 + mi * 16 + (l >> 2) + h * 8;
                const float inv = 1.0f / g_rowsum[row];
                const float* pvrow = p_vlm + (size_t)row * C_CLS;
                float*       orow  = out   + (size_t)row * C_CLS;
                #pragma unroll
                for (int ni = 0; ni < 8; ni++) {
                    const int col = bn + ni * 8 + (l & 3) * 2;
                    #pragma unroll
                    for (int e = 0; e < 2; e++) {
                        int n = col + e;
                        if (n < C_CLS) {
                            float pt  = g_m2[n] * INV_C
                                      + acc[mi][ni][h * 2 + e] * DEQ * inv;
                            float pv  = __ldg(pvrow + n);
                            float eut = __expf(pt * __logf(pt + EPSU));
                            float euv = __expf(pv * __logf(pv + EPSU));
                            orow[n] = (eut * pt + euv * pv) / (eut + euv);
                        }
                    }
                }
            }
        }
    }
}

// ---------------------------------------------------------------------------
extern "C" void kernel_launch(void* const* d_in, const int* in_sizes, int n_in,
                              void* d_out, int out_size) {
    const float* p_tar = (const float*)d_in[0];
    const float* p_vlm = (const float*)d_in[1];
    const float* alpha = (const float*)d_in[2];
    const float* bank  = (const float*)d_in[3];
    float* out      = (float*)d_out;                       // p_mix [B,C]
    float* out_bank = out + (size_t)B_ROWS * C_CLS;        // bank_new [C,C]

    static int attr_set = 0;
    if (!attr_set) {
        cudaFuncSetAttribute(gemm_fp8, cudaFuncAttributeMaxDynamicSharedMemorySize,
                             SMEMT);
        attr_set = 1;
    }

    dim3 gg(KPAD / BN, B_ROWS / BM);  // (16, 256)

    zero_kernel<<<(C_CLS * C_CLS + 255) / 256, 256>>>();          // 1
    convB1_kernel<<<KPAD, 128>>>(bank);                           // 2
    transT_kernel<<<dim3(32, 32), 256>>>(bank);                   // 3
    convB2_kernel<<<KPAD, 128>>>();                               // 4
    prep_kernel<<<B_ROWS, 256>>>(p_tar, p_vlm, out);              // 5
    gemm_fp8<<<gg, 128, SMEMT>>>(nullptr, nullptr, 1);            // 6
    gemm_fp8<<<gg, 128, SMEMT>>>(p_vlm, out, 2);                  // 7
    bank_kernel<<<(C_CLS * C_CLS + 255) / 256, 256>>>(bank, alpha, out_bank); // 8
}

// round 14
// speedup vs baseline: 7.7880x; 1.2302x over previous
#include <cuda_runtime.h>
#include <cuda_bf16.h>
#include <cuda_fp8.h>
#include <cstdint>
#include <math.h>

#define B_ROWS 32768
#define C_CLS  1000
#define KPAD   1024
#define EPSU   1e-6f
#define NORMF  0.031622776601683794f   // 1/sqrt(1000)
#define INV_C  0.001f
#define SA     128.0f                  // fp8 scale for A / E
#define SB     256.0f                  // fp8 scale for centered B residuals
#define DEQ    (1.0f / (128.0f * 256.0f))

// ---------------- scratch (__device__ globals; no allocations) --------------
__device__ uint8_t g_Af8[(size_t)B_ROWS * KPAD];   // p_tar  fp8 x128, padded
__device__ uint8_t g_Ef8[(size_t)B_ROWS * KPAD];   // E      fp8 x128, padded
__device__ uint8_t g_B1f8[(size_t)KPAD * KPAD];    // (bank - m1) x256  [n][k]
__device__ uint8_t g_B2f8[(size_t)KPAD * KPAD];    // (bank^T - m2) x256 [j][k]
__device__ float   g_BT[(size_t)KPAD * KPAD];      // bank^T fp32 staging
__device__ float   g_m1[KPAD];                     // row means of bank
__device__ float   g_m2[KPAD];                     // raw col sums of bank
__device__ float   g_ptc[KPAD];                    // fast-path pt per column
__device__ float   g_eutc[KPAD];                   // fast-path eut per column
__device__ float   g_rowsum[B_ROWS];
__device__ float   g_sums[(size_t)C_CLS * C_CLS];
__device__ float   g_count[C_CLS];
__device__ int     g_nzB1;                         // residual B1 has nonzero?
__device__ int     g_nzB2;                         // residual B2 has nonzero?

// ---------------- helpers ----------------------------------------------------
__device__ __forceinline__ uint16_t f2_fp8x2(float lo, float hi) {
    __nv_fp8x2_storage_t r =
        __nv_cvt_float2_to_fp8x2(make_float2(lo, hi), __NV_SATFINITE, __NV_E4M3);
    return (uint16_t)r;
}
__device__ __forceinline__ uint32_t smem_u32(const void* p) {
    uint32_t a;
    asm("{ .reg .u64 t; cvta.to.shared.u64 t, %1; cvt.u32.u64 %0, t; }"
        : "=r"(a) : "l"(p));
    return a;
}
__device__ __forceinline__ void ldmx4(uint32_t* r, uint32_t addr) {
    asm volatile("ldmatrix.sync.aligned.m8n8.x4.shared.b16 {%0,%1,%2,%3}, [%4];"
                 : "=r"(r[0]), "=r"(r[1]), "=r"(r[2]), "=r"(r[3]) : "r"(addr));
}
__device__ __forceinline__ void mma_fp8(float* c, const uint32_t* a,
                                        uint32_t b0, uint32_t b1) {
    asm volatile("mma.sync.aligned.m16n8k32.row.col.f32.e4m3.e4m3.f32 "
                 "{%0,%1,%2,%3}, {%4,%5,%6,%7}, {%8,%9}, {%0,%1,%2,%3};"
                 : "+f"(c[0]), "+f"(c[1]), "+f"(c[2]), "+f"(c[3])
                 : "r"(a[0]), "r"(a[1]), "r"(a[2]), "r"(a[3]), "r"(b0), "r"(b1));
}
#define CP16(dst, src) \
    asm volatile("cp.async.cg.shared.global [%0], [%1], 16;" :: "r"(dst), "l"(src))
#define CP_COMMIT() asm volatile("cp.async.commit_group;")
#define CP_WAIT1()  asm volatile("cp.async.wait_group 1;")

// ---------------------------------------------------------------------------
__global__ void zero_kernel() {
    int i = blockIdx.x * blockDim.x + threadIdx.x;
    if (i < C_CLS * C_CLS) g_sums[i] = 0.0f;
    if (i < B_ROWS)        g_rowsum[i] = 0.0f;
    if (i < C_CLS)         g_count[i] = 0.0f;
    if (i < KPAD)          g_m2[i] = 0.0f;
    if (i == 0) { g_nzB1 = 0; g_nzB2 = 0; }
}

// B1: row means + centered fp8 residual rows of bank [n][k] + nonzero flag
__global__ void __launch_bounds__(128) convB1_kernel(const float* __restrict__ bank) {
    const int n = blockIdx.x;     // 0..1023
    const int t = threadIdx.x;
    uint32_t* dst = reinterpret_cast<uint32_t*>(g_B1f8 + (size_t)n * KPAD);
    if (n >= C_CLS) {
        for (int u = t; u < KPAD / 4; u += 128) dst[u] = 0u;
        if (t == 0) g_m1[n] = 0.0f;
        return;
    }
    const float* row = bank + (size_t)n * C_CLS;
    float s = 0.0f;
    for (int k = t; k < C_CLS; k += 128) s += row[k];
    #pragma unroll
    for (int o = 16; o > 0; o >>= 1) s += __shfl_xor_sync(0xFFFFFFFFu, s, o);
    __shared__ float sw[4];
    if ((t & 31) == 0) sw[t >> 5] = s;
    __syncthreads();
    const float m = (sw[0] + sw[1] + sw[2] + sw[3]) * INV_C;
    if (t == 0) g_m1[n] = m;
    uint32_t nz = 0u;
    for (int u = t; u < KPAD / 4; u += 128) {
        int k = 4 * u;
        float4 v = make_float4(0.f, 0.f, 0.f, 0.f);
        if (k + 3 < C_CLS) v = *(const float4*)(row + k);  // C_CLS % 4 == 0
        uint16_t lo = f2_fp8x2((k < C_CLS) ? (v.x - m) * SB : 0.f,
                               (k < C_CLS) ? (v.y - m) * SB : 0.f);
        uint16_t hi = f2_fp8x2((k < C_CLS) ? (v.z - m) * SB : 0.f,
                               (k < C_CLS) ? (v.w - m) * SB : 0.f);
        uint32_t packed = (uint32_t)lo | ((uint32_t)hi << 16);
        dst[u] = packed;
        nz |= (packed & 0x7F7F7F7Fu);   // value-zero test (ignore sign of -0)
    }
    if (nz) atomicOr(&g_nzB1, 1);
}

// T1: tiled transpose bank -> g_BT (fp32) + column-sum atomics into g_m2
__global__ void __launch_bounds__(256) transT_kernel(const float* __restrict__ bank) {
    __shared__ float tile[32][33];
    const int tk = blockIdx.y * 32;
    const int tj = blockIdx.x * 32;
    const int jx = threadIdx.x & 31;
    const int ky = threadIdx.x >> 5;
    #pragma unroll
    for (int s = 0; s < 4; s++) {
        int k = tk + ky + s * 8, j = tj + jx;
        tile[ky + s * 8][jx] = (k < C_CLS && j < C_CLS)
                             ? bank[(size_t)k * C_CLS + j] : 0.0f;
    }
    __syncthreads();
    #pragma unroll
    for (int s = 0; s < 4; s++) {
        int j = tj + ky + s * 8, k = tk + jx;
        g_BT[(size_t)j * KPAD + k] = tile[jx][ky + s * 8];
    }
    float ps = 0.0f;
    #pragma unroll
    for (int s = 0; s < 4; s++) ps += tile[ky + s * 8][jx];
    __syncthreads();
    tile[ky][jx] = ps;
    __syncthreads();
    if (ky == 0) {
        float tot = 0.0f;
        #pragma unroll
        for (int y = 0; y < 8; y++) tot += tile[y][jx];
        if (tj + jx < C_CLS) atomicAdd(&g_m2[tj + jx], tot);
    }
}

// T2: centered fp8 residual rows of bank^T [j][k] + nonzero flag
//     + per-column fast-path constants pt[j], eut[j]
__global__ void __launch_bounds__(128) convB2_kernel() {
    const int j = blockIdx.x;
    const int t = threadIdx.x;
    uint32_t* dst = reinterpret_cast<uint32_t*>(g_B2f8 + (size_t)j * KPAD);
    if (j >= C_CLS) {
        for (int u = t; u < KPAD / 4; u += 128) dst[u] = 0u;
        if (t == 0) { g_ptc[j] = 0.0f; g_eutc[j] = 1.0f; }
        return;
    }
    const float m = g_m2[j] * INV_C;
    if (t == 0) {
        g_ptc[j]  = m;
        g_eutc[j] = __expf(m * __logf(m + EPSU));
    }
    const float* row = g_BT + (size_t)j * KPAD;
    uint32_t nz = 0u;
    for (int u = t; u < KPAD / 4; u += 128) {
        int k = 4 * u;
        if (k + 3 < C_CLS) {
            float4 v = *(const float4*)(row + k);
            uint16_t lo = f2_fp8x2((v.x - m) * SB, (v.y - m) * SB);
            uint16_t hi = f2_fp8x2((v.z - m) * SB, (v.w - m) * SB);
            uint32_t packed = (uint32_t)lo | ((uint32_t)hi << 16);
            dst[u] = packed;
            nz |= (packed & 0x7F7F7F7Fu);
        } else {
            dst[u] = 0u;
        }
    }
    if (nz) atomicOr(&g_nzB2, 1);
}

// prep: 4 rows per 256-thread block (64 thr/row, MLP=8):
//   dual argmax + agreement + fused scatter-add
//   + p_tar -> fp8 A (only if gemm1's mainloop will run)
//   + FUSED uncertainty mixing -> out when nzB2 == 0 (p_vlm read exactly once)
#define RPB 4
__global__ void __launch_bounds__(256) prep_kernel(const float* __restrict__ p_tar,
                                                   const float* __restrict__ p_vlm,
                                                   float* __restrict__ out) {
    const int t    = threadIdx.x;
    const int rg   = t >> 6;             // row group 0..3
    const int g    = t & 63;             // thread within row group
    const int row  = blockIdx.x * RPB + rg;
    const int  nzB2  = g_nzB2;
    const bool needA = (g_nzB1 != 0) && (nzB2 != 0);

    const float4* pt4 = reinterpret_cast<const float4*>(p_tar + (size_t)row * C_CLS);
    const float4* pv4 = reinterpret_cast<const float4*>(p_vlm + (size_t)row * C_CLS);
    uint32_t* arow = reinterpret_cast<uint32_t*>(g_Af8 + (size_t)row * KPAD);

    // load 4 chunks per input (MLP = 8 float4 loads in flight)
    float4 a[4], b[4];
    bool   val[4];
    #pragma unroll
    for (int i = 0; i < 4; i++) {
        const int kq = g + 64 * i;       // float4 index, 0..255
        val[i] = (kq < C_CLS / 4);       // C_CLS % 4 == 0 -> 250 valid chunks
        if (val[i]) { a[i] = pt4[kq]; b[i] = pv4[kq]; }
        else        { a[i] = make_float4(0.f,0.f,0.f,0.f);
                      b[i] = make_float4(0.f,0.f,0.f,0.f); }
    }

    float vt = -1.0f, vv = -1.0f;
    int   it = 0,     iv = 0;
    #pragma unroll
    for (int i = 0; i < 4; i++) {
        const int k = 4 * (g + 64 * i);
        if (val[i]) {
            if (a[i].x > vt) { vt = a[i].x; it = k; }
            if (a[i].y > vt) { vt = a[i].y; it = k + 1; }
            if (a[i].z > vt) { vt = a[i].z; it = k + 2; }
            if (a[i].w > vt) { vt = a[i].w; it = k + 3; }
            if (b[i].x > vv) { vv = b[i].x; iv = k; }
            if (b[i].y > vv) { vv = b[i].y; iv = k + 1; }
            if (b[i].z > vv) { vv = b[i].z; iv = k + 2; }
            if (b[i].w > vv) { vv = b[i].w; iv = k + 3; }
        }
        // fp8 A store (covers all 256 uint32 of the padded row)
        if (needA) {
            const int kq = g + 64 * i;
            uint16_t lo = f2_fp8x2(a[i].x * SA, a[i].y * SA);
            uint16_t hi = f2_fp8x2(a[i].z * SA, a[i].w * SA);
            arow[kq] = (uint32_t)lo | ((uint32_t)hi << 16);
        }
        // fast-path mixing (streaming store; out is write-once)
        if (nzB2 == 0 && val[i]) {
            float4 pc = *(const float4*)(g_ptc + k);
            float4 ec = *(const float4*)(g_eutc + k);
            float4 o;
            float euv;
            euv = __expf(b[i].x * __logf(b[i].x + EPSU));
            o.x = (ec.x * pc.x + euv * b[i].x) / (ec.x + euv);
            euv = __expf(b[i].y * __logf(b[i].y + EPSU));
            o.y = (ec.y * pc.y + euv * b[i].y) / (ec.y + euv);
            euv = __expf(b[i].z * __logf(b[i].z + EPSU));
            o.z = (ec.z * pc.z + euv * b[i].z) / (ec.z + euv);
            euv = __expf(b[i].w * __logf(b[i].w + EPSU));
            o.w = (ec.w * pc.w + euv * b[i].w) / (ec.w + euv);
            __stcs(reinterpret_cast<float4*>(out + (size_t)row * C_CLS + k), o);
        }
    }

    // reduce within warp (32 lanes all in same row group)
    #pragma unroll
    for (int off = 16; off > 0; off >>= 1) {
        float ov = __shfl_down_sync(0xFFFFFFFFu, vt, off);
        int   oi = __shfl_down_sync(0xFFFFFFFFu, it, off);
        if (ov > vt || (ov == vt && oi < it)) { vt = ov; it = oi; }
        ov = __shfl_down_sync(0xFFFFFFFFu, vv, off);
        oi = __shfl_down_sync(0xFFFFFFFFu, iv, off);
        if (ov > vv || (ov == vv && oi < iv)) { vv = ov; iv = oi; }
    }
    __shared__ float swt[8], swv[8];
    __shared__ int   sit[8], siv[8];
    __shared__ int   s_lab[RPB];
    const int w = t >> 5;                 // warp id 0..7; row group rg = w>>1
    if ((t & 31) == 0) { swt[w] = vt; sit[w] = it; swv[w] = vv; siv[w] = iv; }
    __syncthreads();
    if (g == 0) {                         // one finalizer per row group
        const int w0 = 2 * rg;
        float bt = swt[w0], bv = swv[w0];
        int   bi = sit[w0], bj = siv[w0];
        if (swt[w0 + 1] > bt || (swt[w0 + 1] == bt && sit[w0 + 1] < bi))
            { bt = swt[w0 + 1]; bi = sit[w0 + 1]; }
        if (swv[w0 + 1] > bv || (swv[w0 + 1] == bv && siv[w0 + 1] < bj))
            { bv = swv[w0 + 1]; bj = siv[w0 + 1]; }
        if (bi == bj) { s_lab[rg] = bi; atomicAdd(&g_count[bi], 1.0f); }
        else          { s_lab[rg] = -1; }
    }
    __syncthreads();
    const int c = s_lab[rg];
    if (c >= 0) {   // fused scatter (rare: ~B/C rows agree)
        float* dst = g_sums + (size_t)c * C_CLS;
        #pragma unroll
        for (int i = 0; i < 4; i++) {
            if (val[i]) {
                const int k = 4 * (g + 64 * i);
                atomicAdd(dst + k + 0, a[i].x);
                atomicAdd(dst + k + 1, a[i].y);
                atomicAdd(dst + k + 2, a[i].z);
                atomicAdd(dst + k + 3, a[i].w);
            }
        }
    }
}

__global__ void bank_kernel(const float* __restrict__ bank,
                            const float* __restrict__ alpha,
                            float* __restrict__ out_bank) {
    int i = blockIdx.x * blockDim.x + threadIdx.x;
    if (i >= C_CLS * C_CLS) return;
    int   c   = i / C_CLS;
    float a   = alpha[0];
    float cnt = g_count[c];
    float b   = bank[i];
    out_bank[i] = (cnt > 0.0f) ? (a * b + (1.0f - a) * (g_sums[i] / cnt)) : b;
}

// ---------------------------------------------------------------------------
// fp8 HMMA GEMM (NT): D[bm:+128, bn:+64] = A * B^T (residual part)
// 128 thr, 4 warps, warp tile 32x64, cp.async 3-stage, 4 CTAs/SM.
// FAST PATHS (exact):
//  - nzB2==0            -> both modes exit (E/rowsum dead; out written by prep)
//  - nzB==0 (general)   -> mainloop skipped, acc stays +0 (bit-identical)
#define BM     128
#define BN     64
#define BKB    64                    // k bytes per chunk
#define STAGES 3
#define LDSPB  80                    // padded smem row stride (bytes)
#define NCH    (KPAD / BKB)          // 16
#define STA    (BM * LDSPB)          // 10240
#define STB    (BN * LDSPB)          // 5120
#define STT    (STA + STB)           // 15360
#define SMEMT  (STAGES * STT)        // 46080

__global__ void __launch_bounds__(128, 4)
gemm_fp8(const float* __restrict__ p_vlm,
         float* __restrict__ out,
         int mode) {
    extern __shared__ char smem[];
    const uint32_t sb = smem_u32(smem);

    const int nzB2 = g_nzB2;
    if (nzB2 == 0) return;   // fast path handled entirely by prep_kernel

    const uint8_t* __restrict__ A  = (mode == 1) ? g_Af8  : g_Ef8;
    const uint8_t* __restrict__ Bm = (mode == 1) ? g_B1f8 : g_B2f8;
    const int nzB = (mode == 1) ? g_nzB1 : nzB2;

    const int t   = threadIdx.x;
    const int wid = t >> 5;              // 0..3 -> m offset wid*32
    const int l   = t & 31;
    const int bm  = blockIdx.y * BM;
    const int bn  = blockIdx.x * BN;

    const int r = t >> 2, u = t & 3;     // loader: 32 rows x 4x16B per pass

    float acc[2][8][4];
    #pragma unroll
    for (int mi = 0; mi < 2; mi++)
        #pragma unroll
        for (int ni = 0; ni < 8; ni++)
            #pragma unroll
            for (int kk = 0; kk < 4; kk++) acc[mi][ni][kk] = 0.0f;

    if (nzB) {   // residual GEMM only when B residual is not value-zero
        const int aRow = wid * 32 + (l & 15);
        const int aOff = (l & 16) ? 16 : 0;   // bytes
        const int bRow = (l & 7) + ((l & 16) ? 8 : 0);
        const int bOff = (l & 8) ? 16 : 0;    // bytes

        auto load_stage = [&](int chunk, int buf) {
            const int kc = chunk * BKB;
            const uint32_t dA = sb + buf * STT;
            const uint32_t dB = dA + STA;
            #pragma unroll
            for (int i = 0; i < 4; i++) {     // A: 128 rows
                int rr = r + 32 * i;
                CP16(dA + rr * LDSPB + u * 16,
                     (const void*)(A + (size_t)(bm + rr) * KPAD + kc + u * 16));
            }
            #pragma unroll
            for (int i = 0; i < 2; i++) {     // B: 64 rows
                int rr = r + 32 * i;
                CP16(dB + rr * LDSPB + u * 16,
                     (const void*)(Bm + (size_t)(bn + rr) * KPAD + kc + u * 16));
            }
        };

        #pragma unroll
        for (int s = 0; s < STAGES - 1; ++s) { load_stage(s, s); CP_COMMIT(); }

        for (int c = 0; c < NCH; ++c) {
            CP_WAIT1();
            __syncthreads();

            const int nc_ = c + STAGES - 1;
            if (nc_ < NCH) load_stage(nc_, nc_ % STAGES);
            CP_COMMIT();

            const int buf = c % STAGES;
            const uint32_t baseA = sb + buf * STT;
            const uint32_t baseB = baseA + STA;

            #pragma unroll
            for (int s = 0; s < 2; ++s) {
                uint32_t af[2][4];
                #pragma unroll
                for (int mi = 0; mi < 2; mi++)
                    ldmx4(af[mi], baseA + (aRow + mi * 16) * LDSPB + s * 32 + aOff);
                uint32_t bf[4][4];
                #pragma unroll
                for (int g2 = 0; g2 < 4; g2++)
                    ldmx4(bf[g2], baseB + (bRow + g2 * 16) * LDSPB + s * 32 + bOff);
                #pragma unroll
                for (int mi = 0; mi < 2; mi++)
                    #pragma unroll
                    for (int g2 = 0; g2 < 4; g2++) {
                        mma_fp8(acc[mi][2 * g2],     af[mi], bf[g2][0], bf[g2][1]);
                        mma_fp8(acc[mi][2 * g2 + 1], af[mi], bf[g2][2], bf[g2][3]);
                    }
            }
        }
    }

    // ---- epilogue (general path) ----
    // rows: bm + wid*32 + mi*16 + (l>>2) + h*8 ; cols: bn + ni*8 + (l&3)*2
    if (mode == 1) {
        #pragma unroll
        for (int mi = 0; mi < 2; mi++) {
            #pragma unroll
            for (int h = 0; h < 2; h++) {
                const int row = bm + wid * 32 + mi * 16 + (l >> 2) + h * 8;
                float rs = 0.0f;
                #pragma unroll
                for (int ni = 0; ni < 8; ni++) {
                    const int col = bn + ni * 8 + (l & 3) * 2;
                    float e0 = 0.0f, e1 = 0.0f;
                    if (col < C_CLS)
                        e0 = __expf((g_m1[col] + acc[mi][ni][h * 2 + 0] * DEQ) * NORMF);
                    if (col + 1 < C_CLS)
                        e1 = __expf((g_m1[col + 1] + acc[mi][ni][h * 2 + 1] * DEQ) * NORMF);
                    *(uint16_t*)&g_Ef8[(size_t)row * KPAD + col] =
                        f2_fp8x2(e0 * SA, e1 * SA);
                    rs += e0 + e1;
                }
                rs += __shfl_xor_sync(0xFFFFFFFFu, rs, 1);
                rs += __shfl_xor_sync(0xFFFFFFFFu, rs, 2);
                if ((l & 3) == 0) atomicAdd(&g_rowsum[row], rs);
            }
        }
    } else {
        #pragma unroll
        for (int mi = 0; mi < 2; mi++) {
            #pragma unroll
            for (int h = 0; h < 2; h++) {
                const int row = bm + wid * 32 + mi * 16 + (l >> 2) + h * 8;
                const float inv = 1.0f / g_rowsum[row];
                const float* pvrow = p_vlm + (size_t)row * C_CLS;
                float*       orow  = out   + (size_t)row * C_CLS;
                #pragma unroll
                for (int ni = 0; ni < 8; ni++) {
                    const int col = bn + ni * 8 + (l & 3) * 2;
                    #pragma unroll
                    for (int e = 0; e < 2; e++) {
                        int n = col + e;
                        if (n < C_CLS) {
                            float pt  = g_m2[n] * INV_C
                                      + acc[mi][ni][h * 2 + e] * DEQ * inv;
                            float pv  = __ldg(pvrow + n);
                            float eut = __expf(pt * __logf(pt + EPSU));
                            float euv = __expf(pv * __logf(pv + EPSU));
                            orow[n] = (eut * pt + euv * pv) / (eut + euv);
                        }
                    }
                }
            }
        }
    }
}

// ---------------------------------------------------------------------------
extern "C" void kernel_launch(void* const* d_in, const int* in_sizes, int n_in,
                              void* d_out, int out_size) {
    const float* p_tar = (const float*)d_in[0];
    const float* p_vlm = (const float*)d_in[1];
    const float* alpha = (const float*)d_in[2];
    const float* bank  = (const float*)d_in[3];
    float* out      = (float*)d_out;                       // p_mix [B,C]
    float* out_bank = out + (size_t)B_ROWS * C_CLS;        // bank_new [C,C]

    static int attr_set = 0;
    if (!attr_set) {
        cudaFuncSetAttribute(gemm_fp8, cudaFuncAttributeMaxDynamicSharedMemorySize,
                             SMEMT);
        attr_set = 1;
    }

    dim3 gg(KPAD / BN, B_ROWS / BM);  // (16, 256)

    zero_kernel<<<(C_CLS * C_CLS + 255) / 256, 256>>>();          // 1
    convB1_kernel<<<KPAD, 128>>>(bank);                           // 2
    transT_kernel<<<dim3(32, 32), 256>>>(bank);                   // 3
    convB2_kernel<<<KPAD, 128>>>();                               // 4
    prep_kernel<<<B_ROWS / RPB, 256>>>(p_tar, p_vlm, out);        // 5
    gemm_fp8<<<gg, 128, SMEMT>>>(nullptr, nullptr, 1);            // 6
    gemm_fp8<<<gg, 128, SMEMT>>>(p_vlm, out, 2);                  // 7
    bank_kernel<<<(C_CLS * C_CLS + 255) / 256, 256>>>(bank, alpha, out_bank); // 8
}